// round 9
// baseline (speedup 1.0000x reference)
#include <cuda_runtime.h>
#include <cuda_bf16.h>
#include <math.h>
#include <cstdint>

#define N_PTS   262144
#define DIM     512
#define HID     256
#define NSEG    64
#define LN_EPS  1e-5f

#define MTILE   256     // rows per score CTA (2 x 128-row MMA tiles)
#define MMA_M   128
#define KC      64      // K-chunk (64 bf16 = 128 B row = SW128 atom width)
#define NCHUNK  (DIM / KC)
#define RD      256     // rows per pooling chunk
#define MAXC    16      // pooling chunks per segment

// ---------------- scratch (static device globals; no runtime allocation) ----
__device__ float          g_s[N_PTS];
__device__ float          g_smax[NSEG];
__device__ float          g_den[NSEG];
__device__ float          g_part[(size_t)NSEG * MAXC * DIM];
__device__ __nv_bfloat16  g_w1hi[HID * DIM];
__device__ __nv_bfloat16  g_w1lo[HID * DIM];

// ---------------- helpers ---------------------------------------------------
__device__ __forceinline__ uint32_t smem_u32(const void* p) {
    uint32_t a;
    asm("{ .reg .u64 t; cvta.to.shared.u64 t, %1; cvt.u32.u64 %0, t; }"
        : "=r"(a) : "l"(p));
    return a;
}
#define SWZ128(o) ((o) ^ (((o) >> 3) & 0x70))

#define CP_ASYNC16(dst, src)                                                   \
    asm volatile("cp.async.cg.shared.global [%0], [%1], 16;" :: "r"(dst), "l"(src))
#define CP_COMMIT() asm volatile("cp.async.commit_group;" ::: "memory")
#define CP_WAIT0()  asm volatile("cp.async.wait_group 0;" ::: "memory")
#define FENCE_ASYNC() asm volatile("fence.proxy.async.shared::cta;" ::: "memory")

__device__ __forceinline__ uint32_t pack_bf2(float a, float b) {
    __nv_bfloat162 t = __floats2bfloat162_rn(a, b);
    return *(uint32_t*)&t;
}
__device__ __forceinline__ float gelu_exact(float h) {
    return 0.5f * h * (1.0f + erff(h * 0.70710678118654752f));
}

// ---------------- tcgen05 helpers (only compiled on sm_103a passes) ---------
#if defined(__CUDA_ARCH_FEAT_SM103_ALL) || defined(__CUDA_ARCH_FEAT_SM100_ALL) || defined(__CUDA_ARCH_FEAT_SM101_ALL)
#define HAVE_TCGEN05 1

__device__ __forceinline__ uint32_t elect_one() {
    uint32_t p;
    asm volatile("{\n\t.reg .pred p;\n\t"
                 "elect.sync _|p, 0xFFFFFFFF;\n\t"
                 "selp.b32 %0, 1, 0, p;\n\t}" : "=r"(p));
    return p;
}
static constexpr uint64_t DESC_BASE_SW128 =
    (uint64_t(2) << 61) | (uint64_t(1) << 46) | (uint64_t(64) << 32) | (uint64_t(1) << 16);
#define MAKE_DESC(addr) (DESC_BASE_SW128 | ((uint64_t)((addr) >> 4) & 0x3FFF))

#define MBAR_INIT(a, c) \
    asm volatile("mbarrier.init.shared.b64 [%0], %1;" :: "r"(a), "r"(c) : "memory")
#define MBAR_WAIT(a, ph) do {                                                  \
    uint32_t _m = (a), _p = (ph), _d;                                          \
    asm volatile("{\n\t.reg .pred p;\n\t"                                      \
        "mbarrier.try_wait.parity.acquire.cta.shared::cta.b64 p, [%1], %2;\n\t"\
        "selp.b32 %0, 1, 0, p;\n\t}" : "=r"(_d) : "r"(_m), "r"(_p) : "memory");\
    if (!_d) {                                                                 \
        asm volatile("{\n\t.reg .pred P1;\n\t"                                 \
          "W%=:\n\t"                                                           \
          "mbarrier.try_wait.parity.acquire.cta.shared::cta.b64 P1, [%0], %1, 0x989680;\n\t" \
          "@P1 bra.uni D%=;\n\t"                                               \
          "bra.uni W%=;\n\t"                                                   \
          "D%=:\n\t}" :: "r"(_m), "r"(_p) : "memory");                         \
    } } while (0)

#define TC_ALLOC(sa, n) \
    asm volatile("tcgen05.alloc.cta_group::1.sync.aligned.shared::cta.b32 [%0], %1;" \
                 :: "r"(sa), "r"(n) : "memory")
#define TC_RELINQ() \
    asm volatile("tcgen05.relinquish_alloc_permit.cta_group::1.sync.aligned;")
#define TC_DEALLOC(t, n) \
    asm volatile("tcgen05.dealloc.cta_group::1.sync.aligned.b32 %0, %1;" :: "r"(t), "r"(n))
#define TC_COMMIT(mb) \
    asm volatile("tcgen05.commit.cta_group::1.mbarrier::arrive::one.shared::cluster.b64 [%0];" \
                 :: "r"(mb) : "memory")
#define TC_FENCE_AFTER()  asm volatile("tcgen05.fence::after_thread_sync;"  ::: "memory")
#define TC_FENCE_BEFORE() asm volatile("tcgen05.fence::before_thread_sync;" ::: "memory")
#define TC_WAIT_LD()      asm volatile("tcgen05.wait::ld.sync.aligned;" ::: "memory")

#define TC_LD_X32(r, ta)                                                       \
    asm volatile("tcgen05.ld.sync.aligned.32x32b.x32.b32 "                     \
        "{%0, %1, %2, %3, %4, %5, %6, %7, "                                    \
        " %8, %9, %10, %11, %12, %13, %14, %15, "                              \
        " %16, %17, %18, %19, %20, %21, %22, %23, "                            \
        " %24, %25, %26, %27, %28, %29, %30, %31}, [%32];"                     \
        : "=r"((r)[0]),  "=r"((r)[1]),  "=r"((r)[2]),  "=r"((r)[3]),           \
          "=r"((r)[4]),  "=r"((r)[5]),  "=r"((r)[6]),  "=r"((r)[7]),           \
          "=r"((r)[8]),  "=r"((r)[9]),  "=r"((r)[10]), "=r"((r)[11]),          \
          "=r"((r)[12]), "=r"((r)[13]), "=r"((r)[14]), "=r"((r)[15]),          \
          "=r"((r)[16]), "=r"((r)[17]), "=r"((r)[18]), "=r"((r)[19]),          \
          "=r"((r)[20]), "=r"((r)[21]), "=r"((r)[22]), "=r"((r)[23]),          \
          "=r"((r)[24]), "=r"((r)[25]), "=r"((r)[26]), "=r"((r)[27]),          \
          "=r"((r)[28]), "=r"((r)[29]), "=r"((r)[30]), "=r"((r)[31])           \
        : "r"(ta))

__device__ __forceinline__ void tc_mma_f16_ss(uint32_t d, uint64_t a, uint64_t b,
                                              uint32_t idesc, bool acc) {
    uint32_t en = acc ? 1u : 0u;
    asm volatile("{\n\t.reg .pred p;\n\t"
                 "setp.ne.u32 p, %5, 0;\n\t"
                 "tcgen05.mma.cta_group::1.kind::f16 [%0], %1, %2, %3, {%4, %4, %4, %4}, p;\n\t}"
                 :: "r"(d), "l"(a), "l"(b), "r"(idesc), "r"(0u), "r"(en)
                 : "memory");
}
// idesc: dtype=F32, a=BF16, b=BF16, N=256, M=128
#define TC_IDESC ((1u << 4) | (1u << 7) | (1u << 10) | ((HID / 8) << 17) | ((MMA_M / 16) << 24))
#endif  // tcgen05

// ---------------- smem layout (bytes) for score_fused -----------------------
#define SM_MU    0        // 256 f32
#define SM_RS    1024
#define SM_LNG   2048     // 512 f32
#define SM_LNB   4096
#define SM_B1    6144     // 256 f32
#define SM_W2    7168
#define SM_TMEM  8192     // tcgen05: TMEM base ptr (4B)
#define SM_MBARB 8200     // tcgen05: mbarrier (8B)
// A: per buf hi 32KB + lo 32KB, double-buffered; B: single buf hi 32KB + lo 32KB
#define SM_A     16384
#define SM_A_LO  32768
#define SM_AB_STRIDE 65536
#define SM_B     147456
#define SM_B_LO  32768
#define SM_TOTAL 212992

// ---------------------------------------------------------------------------
// Kernel 0: convert w1 to bf16 hi/lo pair (tiny)
// ---------------------------------------------------------------------------
__global__ __launch_bounds__(256) void w1cvt_kernel(const float* __restrict__ w1)
{
    int i = (blockIdx.x * 256 + threadIdx.x) * 4;
#pragma unroll
    for (int j = 0; j < 4; j++) {
        float w = w1[i + j];
        __nv_bfloat16 hi = __float2bfloat16_rn(w);
        float lo = w - __bfloat162float(hi);
        g_w1hi[i + j] = hi;
        g_w1lo[i + j] = __float2bfloat16_rn(lo);
    }
}

// ---------------------------------------------------------------------------
// Kernel 1: fused LayerNorm + bf16-split tcgen05 GEMM + GELU + w2 dot -> g_s
// 512 threads, 256 rows x 256 hid per CTA, K=512 in 8 chunks of 64.
// Two 128x256 D tiles in TMEM (cols 0 and 256).
// ---------------------------------------------------------------------------
__global__ __launch_bounds__(512, 1)
void score_fused(const float* __restrict__ feats,
                 const float* __restrict__ lng,
                 const float* __restrict__ lnb,
                 const float* __restrict__ b1,
                 const float* __restrict__ w2,
                 const float* __restrict__ b2)
{
    extern __shared__ char smem[];
    uint32_t sb = smem_u32(smem);
    int tid  = threadIdx.x;
    int w    = tid >> 5, lane = tid & 31;
    int row0 = blockIdx.x * MTILE;

    float* s_mu  = (float*)(smem + SM_MU);
    float* s_rs  = (float*)(smem + SM_RS);
    float* s_lng = (float*)(smem + SM_LNG);
    float* s_lnb = (float*)(smem + SM_LNB);
    float* s_b1  = (float*)(smem + SM_B1);
    float* s_w2  = (float*)(smem + SM_W2);

#ifdef HAVE_TCGEN05
    // =======================================================================
    // tcgen05 path (the one that actually runs on GB300)
    // =======================================================================
    if (w == 0) { TC_ALLOC(sb + SM_TMEM, 512); TC_RELINQ(); }
    if (tid == 0) MBAR_INIT(sb + SM_MBARB, 1);

    for (int i = tid; i < DIM; i += 512) { s_lng[i] = lng[i]; s_lnb[i] = lnb[i]; }
    for (int i = tid; i < HID; i += 512) { s_b1[i] = b1[i]; s_w2[i] = w2[i]; }

    // B staging role: thread = (hid row, 32-col half); 512 thr cover 256x64
    int brow = tid >> 1, bh = tid & 1;
    const __nv_bfloat16* bsrc_h = g_w1hi + (size_t)brow * DIM + bh * 32;
    const __nv_bfloat16* bsrc_l = g_w1lo + (size_t)brow * DIM + bh * 32;
    uint32_t b_sw[4];
#pragma unroll
    for (int j = 0; j < 4; j++) b_sw[j] = SWZ128((uint32_t)(brow * 128 + bh * 64 + j * 16));

#define STAGE_B(cc) do {                                                       \
        const __nv_bfloat16* sh_ = bsrc_h + (cc) * KC;                         \
        const __nv_bfloat16* sl_ = bsrc_l + (cc) * KC;                         \
        _Pragma("unroll")                                                      \
        for (int j = 0; j < 4; j++) {                                          \
            CP_ASYNC16(sb + SM_B + b_sw[j],           sh_ + j * 8);            \
            CP_ASYNC16(sb + SM_B + SM_B_LO + b_sw[j], sl_ + j * 8);            \
        }                                                                      \
    } while (0)

    // kick B(0) before the mean pass (independent of mu/rs)
    STAGE_B(0);
    CP_COMMIT();

    // --- per-row mean / rstd: 16 warps x 16 rows ---
#pragma unroll
    for (int rr = 0; rr < 16; rr++) {
        int row = w * 16 + rr;
        const float4* f4 = (const float4*)(feats + (size_t)(row0 + row) * DIM);
        float sum = 0.f, sq = 0.f;
#pragma unroll
        for (int i = 0; i < 4; i++) {
            float4 v = f4[lane + 32 * i];
            sum += v.x + v.y + v.z + v.w;
            sq  += v.x * v.x + v.y * v.y + v.z * v.z + v.w * v.w;
        }
#pragma unroll
        for (int m = 16; m; m >>= 1) {
            sum += __shfl_xor_sync(0xffffffffu, sum, m);
            sq  += __shfl_xor_sync(0xffffffffu, sq,  m);
        }
        if (lane == 0) {
            float mu = sum * (1.0f / DIM);
            float var = sq * (1.0f / DIM) - mu * mu;
            s_mu[row] = mu;
            s_rs[row] = rsqrtf(var + LN_EPS);
        }
    }
    __syncthreads();

    // A staging: 8 passes, thread = (row = pass*32 + tid>>4, 16B col seg (tid&15)*4)
    int acol = (tid & 15) * 4;       // float index within the 64-col chunk
    int arbase = tid >> 4;           // 0..31

#define STAGE_A(cc, bi) do {                                                   \
        uint32_t ad = SM_A + (bi) * SM_AB_STRIDE;                              \
        float4 g4 = *(const float4*)(s_lng + (cc) * KC + acol);                \
        float4 bb4 = *(const float4*)(s_lnb + (cc) * KC + acol);               \
        _Pragma("unroll")                                                      \
        for (int pass = 0; pass < 8; pass++) {                                 \
            int r = pass * 32 + arbase;                                        \
            float4 f = *(const float4*)(feats + (size_t)(row0 + r) * DIM + (cc) * KC + acol); \
            float mu = s_mu[r], rs = s_rs[r];                                  \
            float x0 = (f.x - mu) * rs * g4.x + bb4.x;                         \
            float x1 = (f.y - mu) * rs * g4.y + bb4.y;                         \
            float x2 = (f.z - mu) * rs * g4.z + bb4.z;                         \
            float x3 = (f.w - mu) * rs * g4.w + bb4.w;                         \
            __nv_bfloat162 h01 = __floats2bfloat162_rn(x0, x1);                \
            __nv_bfloat162 h23 = __floats2bfloat162_rn(x2, x3);                \
            uint2 hv = { *(uint32_t*)&h01, *(uint32_t*)&h23 };                 \
            uint2 lv = { pack_bf2(x0 - __bfloat162float(h01.x),                \
                                  x1 - __bfloat162float(h01.y)),               \
                         pack_bf2(x2 - __bfloat162float(h23.x),                \
                                  x3 - __bfloat162float(h23.y)) };             \
            uint32_t off = (uint32_t)(r * 128 + acol * 2);                     \
            uint32_t sw = SWZ128(off);                                         \
            *(uint2*)(smem + ad + sw)           = hv;                          \
            *(uint2*)(smem + ad + SM_A_LO + sw) = lv;                          \
        }                                                                      \
    } while (0)

    STAGE_A(0, 0);
    CP_WAIT0();
    FENCE_ASYNC();
    __syncthreads();

    uint32_t tmem;
    asm volatile("ld.shared.b32 %0, [%1];" : "=r"(tmem) : "r"(sb + SM_TMEM));

    for (int c = 0; c < NCHUNK; c++) {
        // issue 24 MMA dispatches for chunk c (tile0 rows 0-127, tile1 rows 128-255)
        if (w == 0 && elect_one()) {
            uint32_t abase = sb + SM_A + (c & 1) * SM_AB_STRIDE;
            uint64_t adh0 = MAKE_DESC(abase);
            uint64_t adl0 = MAKE_DESC(abase + SM_A_LO);
            uint64_t adh1 = MAKE_DESC(abase + 16384);            // rows 128-255
            uint64_t adl1 = MAKE_DESC(abase + SM_A_LO + 16384);
            uint64_t bdh  = MAKE_DESC(sb + SM_B);
            uint64_t bdl  = MAKE_DESC(sb + SM_B + SM_B_LO);
            uint32_t d0 = tmem, d1 = tmem + 256;
#pragma unroll
            for (int s = 0; s < 4; s++) {
                bool acc = !(c == 0 && s == 0);
                tc_mma_f16_ss(d0, adh0 + s * 2, bdh + s * 2, TC_IDESC, acc);
                tc_mma_f16_ss(d1, adh1 + s * 2, bdh + s * 2, TC_IDESC, acc);
            }
#pragma unroll
            for (int s = 0; s < 4; s++) {
                tc_mma_f16_ss(d0, adh0 + s * 2, bdl + s * 2, TC_IDESC, true);
                tc_mma_f16_ss(d1, adh1 + s * 2, bdl + s * 2, TC_IDESC, true);
            }
#pragma unroll
            for (int s = 0; s < 4; s++) {
                tc_mma_f16_ss(d0, adl0 + s * 2, bdh + s * 2, TC_IDESC, true);
                tc_mma_f16_ss(d1, adl1 + s * 2, bdh + s * 2, TC_IDESC, true);
            }
            TC_COMMIT(sb + SM_MBARB);
        }
        // stage A(c+1) into the other buffer (safe while MMA(c) runs)
        if (c + 1 < NCHUNK) STAGE_A(c + 1, (c + 1) & 1);
        // wait MMA(c) done, then B buffer is free to restage
        MBAR_WAIT(sb + SM_MBARB, c & 1);
        if (c + 1 < NCHUNK) {
            STAGE_B(c + 1);
            CP_COMMIT();
            CP_WAIT0();
        }
        FENCE_ASYNC();
        __syncthreads();
    }
    TC_FENCE_AFTER();

    // --- epilogue: warps 0-3 -> tile0, warps 4-7 -> tile1 ---
    if (w < 8) {
        int wg  = w >> 2;              // which 128-row tile
        uint32_t dbase = tmem + wg * 256;
        float acc = 0.f;
#pragma unroll
        for (int cb = 0; cb < 8; cb++) {
            uint32_t r[32];
            TC_LD_X32(r, dbase + cb * 32);
            TC_WAIT_LD();
#pragma unroll
            for (int j = 0; j < 32; j++) {
                int col = cb * 32 + j;
                float h = __uint_as_float(r[j]) + s_b1[col];
                acc = fmaf(s_w2[col], gelu_exact(h), acc);
            }
        }
        TC_FENCE_BEFORE();
        g_s[row0 + wg * 128 + (w & 3) * 32 + lane] = acc + b2[0];
    }
    __syncthreads();
    if (w == 0) TC_DEALLOC(tmem, 512);

#else
    // =======================================================================
    // non-sm_103a fallback: trivially correct scalar path (never runs on GB300)
    // =======================================================================
    for (int i = tid; i < DIM; i += 512) { s_lng[i] = lng[i]; s_lnb[i] = lnb[i]; }
    for (int i = tid; i < HID; i += 512) { s_b1[i] = b1[i]; s_w2[i] = w2[i]; }
    __syncthreads();

    int r = row0 + (tid >> 1);
    int h = tid & 1;
    const float* fr = feats + (size_t)r * DIM;
    float sum = 0.f, sq = 0.f;
    for (int k = 0; k < DIM; k++) { float v = fr[k]; sum += v; sq += v * v; }
    float mu = sum * (1.0f / DIM);
    float rs = rsqrtf(sq * (1.0f / DIM) - mu * mu + LN_EPS);
    float acc = 0.f;
    for (int j = h * 128; j < h * 128 + 128; j++) {
        const float* wr = (const float*)0;  // placeholder silenced below
        (void)wr;
        float dot = 0.f;
        for (int k = 0; k < DIM; k++) {
            float x = (fr[k] - mu) * rs * s_lng[k] + s_lnb[k];
            dot = fmaf(x, __bfloat162float(g_w1hi[(size_t)j * DIM + k]) +
                          __bfloat162float(g_w1lo[(size_t)j * DIM + k]), dot);
        }
        acc = fmaf(s_w2[j], gelu_exact(dot + s_b1[j]), acc);
    }
    acc += __shfl_xor_sync(0xffffffffu, acc, 1);
    if (h == 0) g_s[r] = acc + b2[0];
#endif
}

// ---------------------------------------------------------------------------
// Kernel 2: per-segment softmax stats (max, sum of exp)
// ---------------------------------------------------------------------------
__global__ __launch_bounds__(256) void stats_kernel(const int* __restrict__ off)
{
    __shared__ float red[256];
    int s = blockIdx.x;
    int lo = off[s], hi = off[s + 1];
    int tid = threadIdx.x;

    float m = -1e30f;
    for (int i = lo + tid; i < hi; i += 256) m = fmaxf(m, g_s[i]);
    red[tid] = m;
    __syncthreads();
    for (int step = 128; step; step >>= 1) {
        if (tid < step) red[tid] = fmaxf(red[tid], red[tid + step]);
        __syncthreads();
    }
    float M = red[0];
    __syncthreads();

    float sum = 0.f;
    for (int i = lo + tid; i < hi; i += 256) sum += expf(g_s[i] - M);
    red[tid] = sum;
    __syncthreads();
    for (int step = 128; step; step >>= 1) {
        if (tid < step) red[tid] += red[tid + step];
        __syncthreads();
    }
    if (tid == 0) { g_smax[s] = M; g_den[s] = red[0]; }
}

// ---------------------------------------------------------------------------
// Kernel 3: chunked weighted pooling -> deterministic partials
// ---------------------------------------------------------------------------
__global__ __launch_bounds__(256) void pool1_kernel(
    const float* __restrict__ feats, const int* __restrict__ off)
{
    __shared__ float wsm[RD];
    int s = blockIdx.y, c = blockIdx.x;
    int lo = off[s], hi = off[s + 1];
    int tid = threadIdx.x;

    float M   = g_smax[s];
    float inv = 1.0f / g_den[s];
    float ax = 0.f, ay = 0.f, bx = 0.f, by = 0.f;

    for (int r0 = lo + c * RD; r0 < hi; r0 += MAXC * RD) {
        int cnt = min(RD, hi - r0);
        __syncthreads();
        for (int i = tid; i < cnt; i += 256) wsm[i] = expf(g_s[r0 + i] - M) * inv;
        __syncthreads();
        int r = 0;
        for (; r + 8 <= cnt; r += 8) {
#pragma unroll
            for (int u = 0; u < 8; u += 2) {
                float w0 = wsm[r + u], w1v = wsm[r + u + 1];
                float2 v0 = *(const float2*)(feats + (size_t)(r0 + r + u) * DIM + tid * 2);
                float2 v1 = *(const float2*)(feats + (size_t)(r0 + r + u + 1) * DIM + tid * 2);
                ax = fmaf(w0, v0.x, ax); ay = fmaf(w0, v0.y, ay);
                bx = fmaf(w1v, v1.x, bx); by = fmaf(w1v, v1.y, by);
            }
        }
        for (; r < cnt; r++) {
            float wv = wsm[r];
            float2 v = *(const float2*)(feats + (size_t)(r0 + r) * DIM + tid * 2);
            ax = fmaf(wv, v.x, ax); ay = fmaf(wv, v.y, ay);
        }
    }
    float* p = g_part + ((size_t)(s * MAXC + c)) * DIM;
    p[tid * 2]     = ax + bx;
    p[tid * 2 + 1] = ay + by;
}

// ---------------------------------------------------------------------------
// Kernel 4: reduce partials -> out
// ---------------------------------------------------------------------------
__global__ __launch_bounds__(256) void pool2_kernel(float* __restrict__ out)
{
    int s = blockIdx.x, tid = threadIdx.x;
    float ax = 0.f, ay = 0.f;
#pragma unroll
    for (int c = 0; c < MAXC; c++) {
        const float* p = g_part + ((size_t)(s * MAXC + c)) * DIM;
        ax += p[tid * 2];
        ay += p[tid * 2 + 1];
    }
    out[s * DIM + tid * 2]     = ax;
    out[s * DIM + tid * 2 + 1] = ay;
}

// ---------------------------------------------------------------------------
extern "C" void kernel_launch(void* const* d_in, const int* in_sizes, int n_in,
                              void* d_out, int out_size)
{
    const float* feats = (const float*)d_in[0];
    const float* lng   = (const float*)d_in[1];
    const float* lnb   = (const float*)d_in[2];
    const float* w1    = (const float*)d_in[3];
    const float* b1    = (const float*)d_in[4];
    const float* w2    = (const float*)d_in[5];
    const float* b2    = (const float*)d_in[6];
    const int*   off   = (const int*)d_in[7];
    float* out = (float*)d_out;

    static int attr_done = 0;
    if (!attr_done) {
        cudaFuncSetAttribute(score_fused, cudaFuncAttributeMaxDynamicSharedMemorySize, SM_TOTAL);
        attr_done = 1;
    }

    w1cvt_kernel<<<HID * DIM / 1024, 256>>>(w1);
    score_fused<<<N_PTS / MTILE, 512, SM_TOTAL>>>(feats, lng, lnb, b1, w2, b2);
    stats_kernel<<<NSEG, 256>>>(off);
    dim3 g1(MAXC, NSEG);
    pool1_kernel<<<g1, 256>>>(feats, off);
    pool2_kernel<<<NSEG, 256>>>(out);
}

// round 11
// speedup vs baseline: 2.0101x; 2.0101x over previous
#include <cuda_runtime.h>
#include <cuda_bf16.h>
#include <math.h>
#include <cstdint>

#define N_PTS   262144
#define DIM     512
#define HID     256
#define NSEG    64
#define LN_EPS  1e-5f

#define MTILE   128     // rows per score CTA
#define KC      64      // K-chunk (64 bf16 = 128 B row = SW128 atom width)
#define NCHUNK  (DIM / KC)
#define RD      256     // rows per pooling chunk
#define MAXC    16      // pooling chunks per segment

// ---------------- scratch (static device globals; no runtime allocation) ----
__device__ float          g_s[N_PTS];
__device__ float          g_smax[NSEG];
__device__ float          g_den[NSEG];
__device__ float          g_part[(size_t)NSEG * MAXC * DIM];
__device__ __nv_bfloat16  g_w1hi[HID * DIM];   // hi(w1*g)
__device__ __nv_bfloat16  g_w1lo[HID * DIM];   // lo(w1*g)
__device__ float          g_c[HID];            // sum_k w1[j,k]*g[k]
__device__ float          g_d[HID];            // sum_k w1[j,k]*beta[k] + b1[j]

// ---------------- helpers ---------------------------------------------------
__device__ __forceinline__ uint32_t smem_u32(const void* p) {
    uint32_t a;
    asm("{ .reg .u64 t; cvta.to.shared.u64 t, %1; cvt.u32.u64 %0, t; }"
        : "=r"(a) : "l"(p));
    return a;
}
#define SWZ128(o) ((o) ^ (((o) >> 3) & 0x70))

#define CP_ASYNC16(dst, src)                                                   \
    asm volatile("cp.async.cg.shared.global [%0], [%1], 16;" :: "r"(dst), "l"(src))
#define CP_COMMIT() asm volatile("cp.async.commit_group;" ::: "memory")
#define CP_WAIT0()  asm volatile("cp.async.wait_group 0;" ::: "memory")
#define FENCE_ASYNC() asm volatile("fence.proxy.async.shared::cta;" ::: "memory")

__device__ __forceinline__ uint32_t pack_bf2(float a, float b) {
    __nv_bfloat162 t = __floats2bfloat162_rn(a, b);
    return *(uint32_t*)&t;
}
__device__ __forceinline__ float gelu_exact(float h) {
    return 0.5f * h * (1.0f + erff(h * 0.70710678118654752f));
}

// ---------------- tcgen05 helpers (only compiled on sm_103a passes) ---------
#if defined(__CUDA_ARCH_FEAT_SM103_ALL) || defined(__CUDA_ARCH_FEAT_SM100_ALL) || defined(__CUDA_ARCH_FEAT_SM101_ALL)
#define HAVE_TCGEN05 1

__device__ __forceinline__ uint32_t elect_one() {
    uint32_t p;
    asm volatile("{\n\t.reg .pred p;\n\t"
                 "elect.sync _|p, 0xFFFFFFFF;\n\t"
                 "selp.b32 %0, 1, 0, p;\n\t}" : "=r"(p));
    return p;
}
static constexpr uint64_t DESC_BASE_SW128 =
    (uint64_t(2) << 61) | (uint64_t(1) << 46) | (uint64_t(64) << 32) | (uint64_t(1) << 16);
#define MAKE_DESC(addr) (DESC_BASE_SW128 | ((uint64_t)((addr) >> 4) & 0x3FFF))

#define MBAR_INIT(a, c) \
    asm volatile("mbarrier.init.shared.b64 [%0], %1;" :: "r"(a), "r"(c) : "memory")
#define MBAR_WAIT(a, ph) do {                                                  \
    uint32_t _m = (a), _p = (ph), _d;                                          \
    asm volatile("{\n\t.reg .pred p;\n\t"                                      \
        "mbarrier.try_wait.parity.acquire.cta.shared::cta.b64 p, [%1], %2;\n\t"\
        "selp.b32 %0, 1, 0, p;\n\t}" : "=r"(_d) : "r"(_m), "r"(_p) : "memory");\
    if (!_d) {                                                                 \
        asm volatile("{\n\t.reg .pred P1;\n\t"                                 \
          "W%=:\n\t"                                                           \
          "mbarrier.try_wait.parity.acquire.cta.shared::cta.b64 P1, [%0], %1, 0x989680;\n\t" \
          "@P1 bra.uni D%=;\n\t"                                               \
          "bra.uni W%=;\n\t"                                                   \
          "D%=:\n\t}" :: "r"(_m), "r"(_p) : "memory");                         \
    } } while (0)

#define TC_ALLOC(sa, n) \
    asm volatile("tcgen05.alloc.cta_group::1.sync.aligned.shared::cta.b32 [%0], %1;" \
                 :: "r"(sa), "r"(n) : "memory")
#define TC_RELINQ() \
    asm volatile("tcgen05.relinquish_alloc_permit.cta_group::1.sync.aligned;")
#define TC_DEALLOC(t, n) \
    asm volatile("tcgen05.dealloc.cta_group::1.sync.aligned.b32 %0, %1;" :: "r"(t), "r"(n))
#define TC_COMMIT(mb) \
    asm volatile("tcgen05.commit.cta_group::1.mbarrier::arrive::one.shared::cluster.b64 [%0];" \
                 :: "r"(mb) : "memory")
#define TC_FENCE_AFTER()  asm volatile("tcgen05.fence::after_thread_sync;"  ::: "memory")
#define TC_FENCE_BEFORE() asm volatile("tcgen05.fence::before_thread_sync;" ::: "memory")
#define TC_WAIT_LD()      asm volatile("tcgen05.wait::ld.sync.aligned;" ::: "memory")

#define TC_LD_X32(r, ta)                                                       \
    asm volatile("tcgen05.ld.sync.aligned.32x32b.x32.b32 "                     \
        "{%0, %1, %2, %3, %4, %5, %6, %7, "                                    \
        " %8, %9, %10, %11, %12, %13, %14, %15, "                              \
        " %16, %17, %18, %19, %20, %21, %22, %23, "                            \
        " %24, %25, %26, %27, %28, %29, %30, %31}, [%32];"                     \
        : "=r"((r)[0]),  "=r"((r)[1]),  "=r"((r)[2]),  "=r"((r)[3]),           \
          "=r"((r)[4]),  "=r"((r)[5]),  "=r"((r)[6]),  "=r"((r)[7]),           \
          "=r"((r)[8]),  "=r"((r)[9]),  "=r"((r)[10]), "=r"((r)[11]),          \
          "=r"((r)[12]), "=r"((r)[13]), "=r"((r)[14]), "=r"((r)[15]),          \
          "=r"((r)[16]), "=r"((r)[17]), "=r"((r)[18]), "=r"((r)[19]),          \
          "=r"((r)[20]), "=r"((r)[21]), "=r"((r)[22]), "=r"((r)[23]),          \
          "=r"((r)[24]), "=r"((r)[25]), "=r"((r)[26]), "=r"((r)[27]),          \
          "=r"((r)[28]), "=r"((r)[29]), "=r"((r)[30]), "=r"((r)[31])           \
        : "r"(ta))

__device__ __forceinline__ void tc_mma_f16_ss(uint32_t d, uint64_t a, uint64_t b,
                                              uint32_t idesc, bool acc) {
    uint32_t en = acc ? 1u : 0u;
    asm volatile("{\n\t.reg .pred p;\n\t"
                 "setp.ne.u32 p, %5, 0;\n\t"
                 "tcgen05.mma.cta_group::1.kind::f16 [%0], %1, %2, %3, {%4, %4, %4, %4}, p;\n\t}"
                 :: "r"(d), "l"(a), "l"(b), "r"(idesc), "r"(0u), "r"(en)
                 : "memory");
}
// idesc: dtype=F32, a=BF16, b=BF16, N=256, M=128
#define TC_IDESC ((1u << 4) | (1u << 7) | (1u << 10) | ((HID / 8) << 17) | ((MTILE / 16) << 24))
#endif  // tcgen05

// ---------------- smem layout (bytes) for score_fused -----------------------
#define SM_MU    0        // 128 f32
#define SM_RS    512
#define SM_C     1024     // 256 f32: c_j
#define SM_D     2048     // 256 f32: d_j
#define SM_W2    3072     // 256 f32
#define SM_RED   4096     // 512 f32 (epilogue partials)
#define SM_TMEM  6144
#define SM_MBARB 6152
// double-buffered tiles (1024-aligned for SW128)
#define SM_A     16384    // per buf: AHI 16KB + ALO 16KB ; stride 32KB ; x2
#define SM_AB_STRIDE 32768
#define SM_A_LO  16384
#define SM_B     81920    // per buf: BHI 32KB + BLO 32KB ; stride 64KB ; x2
#define SM_BB_STRIDE 65536
#define SM_B_LO  32768
#define SM_TOTAL (SM_B + 2 * SM_BB_STRIDE)   // 212992 B

// ---------------------------------------------------------------------------
// Kernel 0: w1 -> w1*g bf16 hi/lo, plus c_j = sum(w1*g), d_j = sum(w1*beta)+b1
// One block per hid row, 128 threads (4 cols each).
// ---------------------------------------------------------------------------
__global__ __launch_bounds__(128) void w1cvt_kernel(
    const float* __restrict__ w1, const float* __restrict__ lng,
    const float* __restrict__ lnb, const float* __restrict__ b1)
{
    __shared__ float redc[4], redd[4];
    int j = blockIdx.x;
    int t = threadIdx.x;
    int c0 = t * 4;
    float csum = 0.f, dsum = 0.f;
#pragma unroll
    for (int k = 0; k < 4; k++) {
        int c = c0 + k;
        float w = w1[(size_t)j * DIM + c];
        float wt = w * lng[c];
        __nv_bfloat16 hi = __float2bfloat16_rn(wt);
        float lo = wt - __bfloat162float(hi);
        g_w1hi[(size_t)j * DIM + c] = hi;
        g_w1lo[(size_t)j * DIM + c] = __float2bfloat16_rn(lo);
        csum += wt;
        dsum += w * lnb[c];
    }
#pragma unroll
    for (int m = 16; m; m >>= 1) {
        csum += __shfl_xor_sync(0xffffffffu, csum, m);
        dsum += __shfl_xor_sync(0xffffffffu, dsum, m);
    }
    if ((t & 31) == 0) { redc[t >> 5] = csum; redd[t >> 5] = dsum; }
    __syncthreads();
    if (t == 0) {
        g_c[j] = redc[0] + redc[1] + redc[2] + redc[3];
        g_d[j] = redd[0] + redd[1] + redd[2] + redd[3] + b1[j];
    }
}

// ---------------------------------------------------------------------------
// Kernel 1: raw-feats bf16-split tcgen05 GEMM + LN-affine correction + GELU
//           + w2 dot -> g_s.   512 threads, 128 rows x 256 hid per CTA.
// No LayerNorm pre-pass: h = rs*(W~ x) - rs*mu*c + d; row sums accumulated
// during A staging.
// ---------------------------------------------------------------------------
__global__ __launch_bounds__(512, 1)
void score_fused(const float* __restrict__ feats,
                 const float* __restrict__ w2,
                 const float* __restrict__ b2)
{
    extern __shared__ char smem[];
    uint32_t sb = smem_u32(smem);
    int tid  = threadIdx.x;
    int w    = tid >> 5, lane = tid & 31;
    int row0 = blockIdx.x * MTILE;

    float* s_mu  = (float*)(smem + SM_MU);
    float* s_rs  = (float*)(smem + SM_RS);
    float* s_c   = (float*)(smem + SM_C);
    float* s_d   = (float*)(smem + SM_D);
    float* s_w2  = (float*)(smem + SM_W2);
    float* s_red = (float*)(smem + SM_RED);

#ifdef HAVE_TCGEN05
    // =======================================================================
    // tcgen05 path (runs on GB300)
    // =======================================================================
    if (w == 0) { TC_ALLOC(sb + SM_TMEM, 256); TC_RELINQ(); }
    if (tid == 0) MBAR_INIT(sb + SM_MBARB, 1);

    // staging roles
    int arow = tid >> 2, aq = tid & 3;        // A: thread = (row, 16-col quarter)
    int brow = tid >> 1, bh = tid & 1;        // B: thread = (hid row, 32-col half)
    const float* aft = feats + (size_t)(row0 + arow) * DIM + aq * 16;

    uint32_t a_sw  = SWZ128((uint32_t)(arow * 128 + aq * 32));
    uint32_t a_sw2 = SWZ128((uint32_t)(arow * 128 + aq * 32 + 16));
    const __nv_bfloat16* bsrc_h = g_w1hi + (size_t)brow * DIM + bh * 32;
    const __nv_bfloat16* bsrc_l = g_w1lo + (size_t)brow * DIM + bh * 32;
    uint32_t b_sw[4];
#pragma unroll
    for (int j = 0; j < 4; j++) b_sw[j] = SWZ128((uint32_t)(brow * 128 + bh * 64 + j * 16));

#define STAGE_B(cc, bi) do {                                                   \
        uint32_t bd = sb + SM_B + (bi) * SM_BB_STRIDE;                         \
        const __nv_bfloat16* sh_ = bsrc_h + (cc) * KC;                         \
        const __nv_bfloat16* sl_ = bsrc_l + (cc) * KC;                         \
        _Pragma("unroll")                                                      \
        for (int j = 0; j < 4; j++) {                                          \
            CP_ASYNC16(bd + b_sw[j],            sh_ + j * 8);                  \
            CP_ASYNC16(bd + SM_B_LO + b_sw[j],  sl_ + j * 8);                  \
        }                                                                      \
    } while (0)

    float a_sum = 0.f, a_sq = 0.f;   // row-stat accumulators (this thread's slice)

#define STAGE_A(cc, bi) do {                                                   \
        uint32_t ad = SM_A + (bi) * SM_AB_STRIDE;                              \
        const float4* fr = (const float4*)(aft + (cc) * KC);                   \
        _Pragma("unroll")                                                      \
        for (int hblk = 0; hblk < 2; hblk++) {                                 \
            uint32_t hp[4], lp[4];                                             \
            _Pragma("unroll")                                                  \
            for (int j = 0; j < 2; j++) {                                      \
                float4 f = fr[hblk * 2 + j];                                   \
                a_sum += f.x + f.y + f.z + f.w;                                \
                a_sq  += f.x * f.x + f.y * f.y + f.z * f.z + f.w * f.w;        \
                __nv_bfloat162 h01 = __floats2bfloat162_rn(f.x, f.y);          \
                __nv_bfloat162 h23 = __floats2bfloat162_rn(f.z, f.w);          \
                hp[j * 2]     = *(uint32_t*)&h01;                              \
                hp[j * 2 + 1] = *(uint32_t*)&h23;                              \
                lp[j * 2]     = pack_bf2(f.x - __bfloat162float(h01.x),        \
                                         f.y - __bfloat162float(h01.y));       \
                lp[j * 2 + 1] = pack_bf2(f.z - __bfloat162float(h23.x),        \
                                         f.w - __bfloat162float(h23.y));       \
            }                                                                  \
            uint32_t sw = hblk ? a_sw2 : a_sw;                                 \
            *(uint4*)(smem + ad + sw)           = *(uint4*)hp;                 \
            *(uint4*)(smem + ad + SM_A_LO + sw) = *(uint4*)lp;                 \
        }                                                                      \
    } while (0)

    // ---- prologue: stage chunk 0, load params ----
    STAGE_B(0, 0);
    CP_COMMIT();
    STAGE_A(0, 0);
    for (int i = tid; i < HID; i += 512) { s_c[i] = g_c[i]; s_d[i] = g_d[i]; s_w2[i] = w2[i]; }
    CP_WAIT0();
    FENCE_ASYNC();
    __syncthreads();

    uint32_t tmem;
    asm volatile("ld.shared.b32 %0, [%1];" : "=r"(tmem) : "r"(sb + SM_TMEM));

    for (int c = 0; c < NCHUNK; c++) {
        // issue 12 MMA dispatches for chunk c
        if (w == 0 && elect_one()) {
            uint32_t abase = sb + SM_A + (c & 1) * SM_AB_STRIDE;
            uint32_t bbase = sb + SM_B + (c & 1) * SM_BB_STRIDE;
            uint64_t adh = MAKE_DESC(abase);
            uint64_t adl = MAKE_DESC(abase + SM_A_LO);
            uint64_t bdh = MAKE_DESC(bbase);
            uint64_t bdl = MAKE_DESC(bbase + SM_B_LO);
#pragma unroll
            for (int s = 0; s < 4; s++)
                tc_mma_f16_ss(tmem, adh + s * 2, bdh + s * 2, TC_IDESC, !(c == 0 && s == 0));
#pragma unroll
            for (int s = 0; s < 4; s++)
                tc_mma_f16_ss(tmem, adh + s * 2, bdl + s * 2, TC_IDESC, true);
#pragma unroll
            for (int s = 0; s < 4; s++)
                tc_mma_f16_ss(tmem, adl + s * 2, bdh + s * 2, TC_IDESC, true);
            TC_COMMIT(sb + SM_MBARB);
        }
        // before re-staging buffer (c+1)&1 we need MMA(c-1) (which read it) done
        if (c >= 1) MBAR_WAIT(sb + SM_MBARB, (c - 1) & 1);
        if (c + 1 < NCHUNK) {
            STAGE_B(c + 1, (c + 1) & 1);
            CP_COMMIT();
            STAGE_A(c + 1, (c + 1) & 1);
            CP_WAIT0();
            FENCE_ASYNC();
        }
        __syncthreads();
    }

    // finalize row stats while last MMA drains (quad-reduce: lanes aq=0..3 share row)
    a_sum += __shfl_xor_sync(0xffffffffu, a_sum, 1);
    a_sq  += __shfl_xor_sync(0xffffffffu, a_sq,  1);
    a_sum += __shfl_xor_sync(0xffffffffu, a_sum, 2);
    a_sq  += __shfl_xor_sync(0xffffffffu, a_sq,  2);
    if ((lane & 3) == 0) {
        float mu = a_sum * (1.0f / DIM);
        float var = a_sq * (1.0f / DIM) - mu * mu;
        s_mu[arow] = mu;
        s_rs[arow] = rsqrtf(var + LN_EPS);
    }

    MBAR_WAIT(sb + SM_MBARB, (NCHUNK - 1) & 1);
    TC_FENCE_AFTER();
    __syncthreads();

    // --- epilogue: 16 warps; warp w -> rows (w&3)*32, cols (w>>2)*64 ---
    {
        int rsub = w & 3, q = w >> 2;
        uint32_t r0_[32], r1_[32];
        TC_LD_X32(r0_, tmem + q * 64);
        TC_LD_X32(r1_, tmem + q * 64 + 32);
        TC_WAIT_LD();
        int row = rsub * 32 + lane;
        float rs = s_rs[row];
        float nrsmu = -rs * s_mu[row];
        float acc = 0.f;
#pragma unroll
        for (int j = 0; j < 32; j++) {
            int col = q * 64 + j;
            float h = fmaf(rs, __uint_as_float(r0_[j]), fmaf(nrsmu, s_c[col], s_d[col]));
            acc = fmaf(s_w2[col], gelu_exact(h), acc);
        }
#pragma unroll
        for (int j = 0; j < 32; j++) {
            int col = q * 64 + 32 + j;
            float h = fmaf(rs, __uint_as_float(r1_[j]), fmaf(nrsmu, s_c[col], s_d[col]));
            acc = fmaf(s_w2[col], gelu_exact(h), acc);
        }
        TC_FENCE_BEFORE();
        s_red[q * 128 + row] = acc;
    }
    __syncthreads();
    if (tid < MTILE) {
        float s = s_red[tid] + s_red[128 + tid] + s_red[256 + tid] + s_red[384 + tid];
        g_s[row0 + tid] = s + b2[0];
    }
    if (w == 0) TC_DEALLOC(tmem, 256);

#else
    // =======================================================================
    // non-sm_103a fallback: trivially correct scalar path (never runs on GB300)
    // =======================================================================
    for (int i = tid; i < HID; i += 512) { s_c[i] = g_c[i]; s_d[i] = g_d[i]; s_w2[i] = w2[i]; }
    __syncthreads();
    if (tid < MTILE) {
        int row = row0 + tid;
        const float* fr = feats + (size_t)row * DIM;
        float sum = 0.f, sq = 0.f;
        for (int k = 0; k < DIM; k++) { float v = fr[k]; sum += v; sq += v * v; }
        float mu = sum * (1.0f / DIM);
        float rs = rsqrtf(sq * (1.0f / DIM) - mu * mu + LN_EPS);
        float acc = 0.f;
        for (int j = 0; j < HID; j++) {
            float dot = 0.f;
            for (int k = 0; k < DIM; k++) {
                float wt = __bfloat162float(g_w1hi[(size_t)j * DIM + k]) +
                           __bfloat162float(g_w1lo[(size_t)j * DIM + k]);
                dot = fmaf(wt, fr[k], dot);
            }
            float h = rs * dot - rs * mu * s_c[j] + s_d[j];
            acc = fmaf(s_w2[j], gelu_exact(h), acc);
        }
        g_s[row] = acc + b2[0];
    }
#endif
}

// ---------------------------------------------------------------------------
// Kernel 2: per-segment softmax stats (max, sum of exp)
// ---------------------------------------------------------------------------
__global__ __launch_bounds__(256) void stats_kernel(const int* __restrict__ off)
{
    __shared__ float red[256];
    int s = blockIdx.x;
    int lo = off[s], hi = off[s + 1];
    int tid = threadIdx.x;

    float m = -1e30f;
    for (int i = lo + tid; i < hi; i += 256) m = fmaxf(m, g_s[i]);
    red[tid] = m;
    __syncthreads();
    for (int step = 128; step; step >>= 1) {
        if (tid < step) red[tid] = fmaxf(red[tid], red[tid + step]);
        __syncthreads();
    }
    float M = red[0];
    __syncthreads();

    float sum = 0.f;
    for (int i = lo + tid; i < hi; i += 256) sum += expf(g_s[i] - M);
    red[tid] = sum;
    __syncthreads();
    for (int step = 128; step; step >>= 1) {
        if (tid < step) red[tid] += red[tid + step];
        __syncthreads();
    }
    if (tid == 0) { g_smax[s] = M; g_den[s] = red[0]; }
}

// ---------------------------------------------------------------------------
// Kernel 3: chunked weighted pooling -> deterministic partials
// ---------------------------------------------------------------------------
__global__ __launch_bounds__(256) void pool1_kernel(
    const float* __restrict__ feats, const int* __restrict__ off)
{
    __shared__ float wsm[RD];
    int s = blockIdx.y, c = blockIdx.x;
    int lo = off[s], hi = off[s + 1];
    int tid = threadIdx.x;

    float M   = g_smax[s];
    float inv = 1.0f / g_den[s];
    float ax = 0.f, ay = 0.f, bx = 0.f, by = 0.f;

    for (int r0 = lo + c * RD; r0 < hi; r0 += MAXC * RD) {
        int cnt = min(RD, hi - r0);
        __syncthreads();
        for (int i = tid; i < cnt; i += 256) wsm[i] = expf(g_s[r0 + i] - M) * inv;
        __syncthreads();
        int r = 0;
        for (; r + 8 <= cnt; r += 8) {
#pragma unroll
            for (int u = 0; u < 8; u += 2) {
                float w0 = wsm[r + u], w1v = wsm[r + u + 1];
                float2 v0 = *(const float2*)(feats + (size_t)(r0 + r + u) * DIM + tid * 2);
                float2 v1 = *(const float2*)(feats + (size_t)(r0 + r + u + 1) * DIM + tid * 2);
                ax = fmaf(w0, v0.x, ax); ay = fmaf(w0, v0.y, ay);
                bx = fmaf(w1v, v1.x, bx); by = fmaf(w1v, v1.y, by);
            }
        }
        for (; r < cnt; r++) {
            float wv = wsm[r];
            float2 v = *(const float2*)(feats + (size_t)(r0 + r) * DIM + tid * 2);
            ax = fmaf(wv, v.x, ax); ay = fmaf(wv, v.y, ay);
        }
    }
    float* p = g_part + ((size_t)(s * MAXC + c)) * DIM;
    p[tid * 2]     = ax + bx;
    p[tid * 2 + 1] = ay + by;
}

// ---------------------------------------------------------------------------
// Kernel 4: reduce partials -> out
// ---------------------------------------------------------------------------
__global__ __launch_bounds__(256) void pool2_kernel(float* __restrict__ out)
{
    int s = blockIdx.x, tid = threadIdx.x;
    float ax = 0.f, ay = 0.f;
#pragma unroll
    for (int c = 0; c < MAXC; c++) {
        const float* p = g_part + ((size_t)(s * MAXC + c)) * DIM;
        ax += p[tid * 2];
        ay += p[tid * 2 + 1];
    }
    out[s * DIM + tid * 2]     = ax;
    out[s * DIM + tid * 2 + 1] = ay;
}

// ---------------------------------------------------------------------------
extern "C" void kernel_launch(void* const* d_in, const int* in_sizes, int n_in,
                              void* d_out, int out_size)
{
    const float* feats = (const float*)d_in[0];
    const float* lng   = (const float*)d_in[1];
    const float* lnb   = (const float*)d_in[2];
    const float* w1    = (const float*)d_in[3];
    const float* b1    = (const float*)d_in[4];
    const float* w2    = (const float*)d_in[5];
    const float* b2    = (const float*)d_in[6];
    const int*   off   = (const int*)d_in[7];
    float* out = (float*)d_out;

    static int attr_done = 0;
    if (!attr_done) {
        cudaFuncSetAttribute(score_fused, cudaFuncAttributeMaxDynamicSharedMemorySize, SM_TOTAL);
        attr_done = 1;
    }

    w1cvt_kernel<<<HID, 128>>>(w1, lng, lnb, b1);
    score_fused<<<N_PTS / MTILE, 512, SM_TOTAL>>>(feats, w2, b2);
    stats_kernel<<<NSEG, 256>>>(off);
    dim3 g1(MAXC, NSEG);
    pool1_kernel<<<g1, 256>>>(feats, off);
    pool2_kernel<<<NSEG, 256>>>(out);
}

// round 12
// speedup vs baseline: 2.1214x; 1.0553x over previous
#include <cuda_runtime.h>
#include <cuda_bf16.h>
#include <math.h>
#include <cstdint>

#define N_PTS   262144
#define DIM     512
#define HID     256
#define NSEG    64
#define LN_EPS  1e-5f

#define MTILE   128     // rows per score CTA
#define KC      64      // K-chunk (64 bf16 = 128 B row = SW128 atom width)
#define NCHUNK  (DIM / KC)
#define RD      256     // rows per pooling chunk
#define MAXC    16      // pooling chunks per segment

// ---------------- scratch (static device globals; no runtime allocation) ----
__device__ float          g_s[N_PTS];
__device__ float          g_smax[NSEG];
__device__ float          g_den[NSEG];
__device__ float          g_part[(size_t)NSEG * MAXC * DIM];
__device__ __nv_bfloat16  g_w1hi[HID * DIM];   // hi(w1*g)
__device__ __nv_bfloat16  g_w1lo[HID * DIM];   // lo(w1*g)
__device__ float          g_c[HID];            // sum_k w1[j,k]*g[k]
__device__ float          g_d[HID];            // sum_k w1[j,k]*beta[k] + b1[j]

// ---------------- helpers ---------------------------------------------------
__device__ __forceinline__ uint32_t smem_u32(const void* p) {
    uint32_t a;
    asm("{ .reg .u64 t; cvta.to.shared.u64 t, %1; cvt.u32.u64 %0, t; }"
        : "=r"(a) : "l"(p));
    return a;
}
#define SWZ128(o) ((o) ^ (((o) >> 3) & 0x70))

#define CP_ASYNC16(dst, src)                                                   \
    asm volatile("cp.async.cg.shared.global [%0], [%1], 16;" :: "r"(dst), "l"(src))
#define CP_COMMIT() asm volatile("cp.async.commit_group;" ::: "memory")
#define CP_WAIT0()  asm volatile("cp.async.wait_group 0;" ::: "memory")
#define FENCE_ASYNC() asm volatile("fence.proxy.async.shared::cta;" ::: "memory")

__device__ __forceinline__ uint32_t pack_bf2(float a, float b) {
    __nv_bfloat162 t = __floats2bfloat162_rn(a, b);
    return *(uint32_t*)&t;
}
__device__ __forceinline__ float gelu_exact(float h) {
    return 0.5f * h * (1.0f + erff(h * 0.70710678118654752f));
}

// ---------------- tcgen05 helpers (only compiled on sm_103a passes) ---------
#if defined(__CUDA_ARCH_FEAT_SM103_ALL) || defined(__CUDA_ARCH_FEAT_SM100_ALL) || defined(__CUDA_ARCH_FEAT_SM101_ALL)
#define HAVE_TCGEN05 1

__device__ __forceinline__ uint32_t elect_one() {
    uint32_t p;
    asm volatile("{\n\t.reg .pred p;\n\t"
                 "elect.sync _|p, 0xFFFFFFFF;\n\t"
                 "selp.b32 %0, 1, 0, p;\n\t}" : "=r"(p));
    return p;
}
static constexpr uint64_t DESC_BASE_SW128 =
    (uint64_t(2) << 61) | (uint64_t(1) << 46) | (uint64_t(64) << 32) | (uint64_t(1) << 16);
#define MAKE_DESC(addr) (DESC_BASE_SW128 | ((uint64_t)((addr) >> 4) & 0x3FFF))

#define MBAR_INIT(a, c) \
    asm volatile("mbarrier.init.shared.b64 [%0], %1;" :: "r"(a), "r"(c) : "memory")
#define MBAR_WAIT(a, ph) do {                                                  \
    uint32_t _m = (a), _p = (ph), _d;                                          \
    asm volatile("{\n\t.reg .pred p;\n\t"                                      \
        "mbarrier.try_wait.parity.acquire.cta.shared::cta.b64 p, [%1], %2;\n\t"\
        "selp.b32 %0, 1, 0, p;\n\t}" : "=r"(_d) : "r"(_m), "r"(_p) : "memory");\
    if (!_d) {                                                                 \
        asm volatile("{\n\t.reg .pred P1;\n\t"                                 \
          "W%=:\n\t"                                                           \
          "mbarrier.try_wait.parity.acquire.cta.shared::cta.b64 P1, [%0], %1, 0x989680;\n\t" \
          "@P1 bra.uni D%=;\n\t"                                               \
          "bra.uni W%=;\n\t"                                                   \
          "D%=:\n\t}" :: "r"(_m), "r"(_p) : "memory");                         \
    } } while (0)

#define TC_ALLOC(sa, n) \
    asm volatile("tcgen05.alloc.cta_group::1.sync.aligned.shared::cta.b32 [%0], %1;" \
                 :: "r"(sa), "r"(n) : "memory")
#define TC_RELINQ() \
    asm volatile("tcgen05.relinquish_alloc_permit.cta_group::1.sync.aligned;")
#define TC_DEALLOC(t, n) \
    asm volatile("tcgen05.dealloc.cta_group::1.sync.aligned.b32 %0, %1;" :: "r"(t), "r"(n))
#define TC_COMMIT(mb) \
    asm volatile("tcgen05.commit.cta_group::1.mbarrier::arrive::one.shared::cluster.b64 [%0];" \
                 :: "r"(mb) : "memory")
#define TC_FENCE_AFTER()  asm volatile("tcgen05.fence::after_thread_sync;"  ::: "memory")
#define TC_FENCE_BEFORE() asm volatile("tcgen05.fence::before_thread_sync;" ::: "memory")
#define TC_WAIT_LD()      asm volatile("tcgen05.wait::ld.sync.aligned;" ::: "memory")

#define TC_LD_X32(r, ta)                                                       \
    asm volatile("tcgen05.ld.sync.aligned.32x32b.x32.b32 "                     \
        "{%0, %1, %2, %3, %4, %5, %6, %7, "                                    \
        " %8, %9, %10, %11, %12, %13, %14, %15, "                              \
        " %16, %17, %18, %19, %20, %21, %22, %23, "                            \
        " %24, %25, %26, %27, %28, %29, %30, %31}, [%32];"                     \
        : "=r"((r)[0]),  "=r"((r)[1]),  "=r"((r)[2]),  "=r"((r)[3]),           \
          "=r"((r)[4]),  "=r"((r)[5]),  "=r"((r)[6]),  "=r"((r)[7]),           \
          "=r"((r)[8]),  "=r"((r)[9]),  "=r"((r)[10]), "=r"((r)[11]),          \
          "=r"((r)[12]), "=r"((r)[13]), "=r"((r)[14]), "=r"((r)[15]),          \
          "=r"((r)[16]), "=r"((r)[17]), "=r"((r)[18]), "=r"((r)[19]),          \
          "=r"((r)[20]), "=r"((r)[21]), "=r"((r)[22]), "=r"((r)[23]),          \
          "=r"((r)[24]), "=r"((r)[25]), "=r"((r)[26]), "=r"((r)[27]),          \
          "=r"((r)[28]), "=r"((r)[29]), "=r"((r)[30]), "=r"((r)[31])           \
        : "r"(ta))

__device__ __forceinline__ void tc_mma_f16_ss(uint32_t d, uint64_t a, uint64_t b,
                                              uint32_t idesc, bool acc) {
    uint32_t en = acc ? 1u : 0u;
    asm volatile("{\n\t.reg .pred p;\n\t"
                 "setp.ne.u32 p, %5, 0;\n\t"
                 "tcgen05.mma.cta_group::1.kind::f16 [%0], %1, %2, %3, {%4, %4, %4, %4}, p;\n\t}"
                 :: "r"(d), "l"(a), "l"(b), "r"(idesc), "r"(0u), "r"(en)
                 : "memory");
}
// idesc: dtype=F32, a=BF16, b=BF16, N=256, M=128
#define TC_IDESC ((1u << 4) | (1u << 7) | (1u << 10) | ((HID / 8) << 17) | ((MTILE / 16) << 24))
#endif  // tcgen05

// ---------------- smem layout (bytes) for score_fused -----------------------
// misc params < 8 KB, then SINGLE-buffered tiles (2 CTAs/SM fit: 104 KB each)
#define SM_MU    0        // 128 f32
#define SM_RS    512
#define SM_C     1024     // 256 f32: c_j
#define SM_D     2048     // 256 f32: d_j
#define SM_W2    3072     // 256 f32
#define SM_RED   4096     // 512 f32 (epilogue partials)
#define SM_TMEM  6144
#define SM_MBARB 6152
#define SM_A     8192     // AHI 16KB @ +0, ALO 16KB @ +16384 ; ends 40960
#define SM_A_LO  16384
#define SM_B     40960    // BHI 32KB @ +0, BLO 32KB @ +32768 ; ends 106496
#define SM_B_LO  32768
#define SM_TOTAL 106496   // x2 CTAs = 212992 <= 228KB carveout

// ---------------------------------------------------------------------------
// Kernel 0: w1 -> w1*g bf16 hi/lo, plus c_j = sum(w1*g), d_j = sum(w1*beta)+b1
// ---------------------------------------------------------------------------
__global__ __launch_bounds__(128) void w1cvt_kernel(
    const float* __restrict__ w1, const float* __restrict__ lng,
    const float* __restrict__ lnb, const float* __restrict__ b1)
{
    __shared__ float redc[4], redd[4];
    int j = blockIdx.x;
    int t = threadIdx.x;
    int c0 = t * 4;
    float csum = 0.f, dsum = 0.f;
#pragma unroll
    for (int k = 0; k < 4; k++) {
        int c = c0 + k;
        float w = w1[(size_t)j * DIM + c];
        float wt = w * lng[c];
        __nv_bfloat16 hi = __float2bfloat16_rn(wt);
        float lo = wt - __bfloat162float(hi);
        g_w1hi[(size_t)j * DIM + c] = hi;
        g_w1lo[(size_t)j * DIM + c] = __float2bfloat16_rn(lo);
        csum += wt;
        dsum += w * lnb[c];
    }
#pragma unroll
    for (int m = 16; m; m >>= 1) {
        csum += __shfl_xor_sync(0xffffffffu, csum, m);
        dsum += __shfl_xor_sync(0xffffffffu, dsum, m);
    }
    if ((t & 31) == 0) { redc[t >> 5] = csum; redd[t >> 5] = dsum; }
    __syncthreads();
    if (t == 0) {
        g_c[j] = redc[0] + redc[1] + redc[2] + redc[3];
        g_d[j] = redd[0] + redd[1] + redd[2] + redd[3] + b1[j];
    }
}

// ---------------------------------------------------------------------------
// Kernel 1: raw-feats bf16-split tcgen05 GEMM + LN-affine correction + GELU
//           + w2 dot -> g_s.  512 threads, 128x256 per CTA, 2 CTAs/SM.
// Single-buffered tiles; cross-CTA overlap hides per-chunk serialization.
// ---------------------------------------------------------------------------
__global__ __launch_bounds__(512, 2)
void score_fused(const float* __restrict__ feats,
                 const float* __restrict__ w2,
                 const float* __restrict__ b2)
{
    extern __shared__ char smem[];
    uint32_t sb = smem_u32(smem);
    int tid  = threadIdx.x;
    int w    = tid >> 5, lane = tid & 31;
    int row0 = blockIdx.x * MTILE;

    float* s_mu  = (float*)(smem + SM_MU);
    float* s_rs  = (float*)(smem + SM_RS);
    float* s_c   = (float*)(smem + SM_C);
    float* s_d   = (float*)(smem + SM_D);
    float* s_w2  = (float*)(smem + SM_W2);
    float* s_red = (float*)(smem + SM_RED);

#ifdef HAVE_TCGEN05
    // =======================================================================
    // tcgen05 path (runs on GB300)
    // =======================================================================
    if (w == 0) { TC_ALLOC(sb + SM_TMEM, 256); TC_RELINQ(); }
    if (tid == 0) MBAR_INIT(sb + SM_MBARB, 1);

    // staging roles
    int arow = tid >> 2, aq = tid & 3;        // A: thread = (row, 16-col quarter)
    int brow = tid >> 1, bh = tid & 1;        // B: thread = (hid row, 32-col half)
    const float* aft = feats + (size_t)(row0 + arow) * DIM + aq * 16;

    uint32_t a_sw  = SWZ128((uint32_t)(arow * 128 + aq * 32));
    uint32_t a_sw2 = SWZ128((uint32_t)(arow * 128 + aq * 32 + 16));
    const __nv_bfloat16* bsrc_h = g_w1hi + (size_t)brow * DIM + bh * 32;
    const __nv_bfloat16* bsrc_l = g_w1lo + (size_t)brow * DIM + bh * 32;
    uint32_t b_sw[4];
#pragma unroll
    for (int j = 0; j < 4; j++) b_sw[j] = SWZ128((uint32_t)(brow * 128 + bh * 64 + j * 16));

#define STAGE_B(cc) do {                                                       \
        const __nv_bfloat16* sh_ = bsrc_h + (cc) * KC;                         \
        const __nv_bfloat16* sl_ = bsrc_l + (cc) * KC;                         \
        _Pragma("unroll")                                                      \
        for (int j = 0; j < 4; j++) {                                          \
            CP_ASYNC16(sb + SM_B + b_sw[j],           sh_ + j * 8);            \
            CP_ASYNC16(sb + SM_B + SM_B_LO + b_sw[j], sl_ + j * 8);            \
        }                                                                      \
    } while (0)

    float a_sum = 0.f, a_sq = 0.f;   // row-stat accumulators (this thread's slice)

#define STAGE_A(cc) do {                                                       \
        const float4* fr = (const float4*)(aft + (cc) * KC);                   \
        _Pragma("unroll")                                                      \
        for (int hblk = 0; hblk < 2; hblk++) {                                 \
            uint32_t hp[4], lp[4];                                             \
            _Pragma("unroll")                                                  \
            for (int j = 0; j < 2; j++) {                                      \
                float4 f = fr[hblk * 2 + j];                                   \
                a_sum += f.x + f.y + f.z + f.w;                                \
                a_sq  += f.x * f.x + f.y * f.y + f.z * f.z + f.w * f.w;        \
                __nv_bfloat162 h01 = __floats2bfloat162_rn(f.x, f.y);          \
                __nv_bfloat162 h23 = __floats2bfloat162_rn(f.z, f.w);          \
                hp[j * 2]     = *(uint32_t*)&h01;                              \
                hp[j * 2 + 1] = *(uint32_t*)&h23;                              \
                lp[j * 2]     = pack_bf2(f.x - __bfloat162float(h01.x),        \
                                         f.y - __bfloat162float(h01.y));       \
                lp[j * 2 + 1] = pack_bf2(f.z - __bfloat162float(h23.x),        \
                                         f.w - __bfloat162float(h23.y));       \
            }                                                                  \
            uint32_t sw = hblk ? a_sw2 : a_sw;                                 \
            *(uint4*)(smem + SM_A + sw)           = *(uint4*)hp;               \
            *(uint4*)(smem + SM_A + SM_A_LO + sw) = *(uint4*)lp;               \
        }                                                                      \
    } while (0)

    // ---- prologue: stage chunk 0, load params ----
    STAGE_B(0);
    CP_COMMIT();
    STAGE_A(0);
    for (int i = tid; i < HID; i += 512) { s_c[i] = g_c[i]; s_d[i] = g_d[i]; s_w2[i] = w2[i]; }
    CP_WAIT0();
    FENCE_ASYNC();
    __syncthreads();

    uint32_t tmem;
    asm volatile("ld.shared.b32 %0, [%1];" : "=r"(tmem) : "r"(sb + SM_TMEM));

    for (int c = 0; c < NCHUNK; c++) {
        // issue 12 MMA dispatches for chunk c (buffers staged & fenced)
        if (w == 0 && elect_one()) {
            uint64_t adh = MAKE_DESC(sb + SM_A);
            uint64_t adl = MAKE_DESC(sb + SM_A + SM_A_LO);
            uint64_t bdh = MAKE_DESC(sb + SM_B);
            uint64_t bdl = MAKE_DESC(sb + SM_B + SM_B_LO);
#pragma unroll
            for (int s = 0; s < 4; s++)
                tc_mma_f16_ss(tmem, adh + s * 2, bdh + s * 2, TC_IDESC, !(c == 0 && s == 0));
#pragma unroll
            for (int s = 0; s < 4; s++)
                tc_mma_f16_ss(tmem, adh + s * 2, bdl + s * 2, TC_IDESC, true);
#pragma unroll
            for (int s = 0; s < 4; s++)
                tc_mma_f16_ss(tmem, adl + s * 2, bdh + s * 2, TC_IDESC, true);
            TC_COMMIT(sb + SM_MBARB);
        }
        // wait MMA(c) done -> single buffers free to restage
        MBAR_WAIT(sb + SM_MBARB, c & 1);
        if (c + 1 < NCHUNK) {
            STAGE_B(c + 1);
            CP_COMMIT();
            STAGE_A(c + 1);
            CP_WAIT0();
            FENCE_ASYNC();
        }
        __syncthreads();
    }

    // finalize row stats (quad-reduce: lanes aq=0..3 share row)
    a_sum += __shfl_xor_sync(0xffffffffu, a_sum, 1);
    a_sq  += __shfl_xor_sync(0xffffffffu, a_sq,  1);
    a_sum += __shfl_xor_sync(0xffffffffu, a_sum, 2);
    a_sq  += __shfl_xor_sync(0xffffffffu, a_sq,  2);
    if ((lane & 3) == 0) {
        float mu = a_sum * (1.0f / DIM);
        float var = a_sq * (1.0f / DIM) - mu * mu;
        s_mu[arow] = mu;
        s_rs[arow] = rsqrtf(var + LN_EPS);
    }
    TC_FENCE_AFTER();
    __syncthreads();

    // --- epilogue: 16 warps; warp w -> rows (w&3)*32, cols (w>>2)*64 ---
    // one LDTM.x32 in flight at a time (64-reg cap at 2 CTAs/SM)
    {
        int rsub = w & 3, q = w >> 2;
        int row = rsub * 32 + lane;
        float rs = s_rs[row];
        float nrsmu = -rs * s_mu[row];
        float acc = 0.f;
#pragma unroll
        for (int half = 0; half < 2; half++) {
            uint32_t r_[32];
            TC_LD_X32(r_, tmem + q * 64 + half * 32);
            TC_WAIT_LD();
#pragma unroll
            for (int j = 0; j < 32; j++) {
                int col = q * 64 + half * 32 + j;
                float h = fmaf(rs, __uint_as_float(r_[j]), fmaf(nrsmu, s_c[col], s_d[col]));
                acc = fmaf(s_w2[col], gelu_exact(h), acc);
            }
        }
        TC_FENCE_BEFORE();
        s_red[q * 128 + row] = acc;
    }
    __syncthreads();
    if (tid < MTILE) {
        float s = s_red[tid] + s_red[128 + tid] + s_red[256 + tid] + s_red[384 + tid];
        g_s[row0 + tid] = s + b2[0];
    }
    if (w == 0) TC_DEALLOC(tmem, 256);

#else
    // =======================================================================
    // non-sm_103a fallback: trivially correct scalar path (never runs on GB300)
    // =======================================================================
    for (int i = tid; i < HID; i += 512) { s_c[i] = g_c[i]; s_d[i] = g_d[i]; s_w2[i] = w2[i]; }
    __syncthreads();
    if (tid < MTILE) {
        int row = row0 + tid;
        const float* fr = feats + (size_t)row * DIM;
        float sum = 0.f, sq = 0.f;
        for (int k = 0; k < DIM; k++) { float v = fr[k]; sum += v; sq += v * v; }
        float mu = sum * (1.0f / DIM);
        float rs = rsqrtf(sq * (1.0f / DIM) - mu * mu + LN_EPS);
        float acc = 0.f;
        for (int j = 0; j < HID; j++) {
            float dot = 0.f;
            for (int k = 0; k < DIM; k++) {
                float wt = __bfloat162float(g_w1hi[(size_t)j * DIM + k]) +
                           __bfloat162float(g_w1lo[(size_t)j * DIM + k]);
                dot = fmaf(wt, fr[k], dot);
            }
            float h = rs * dot - rs * mu * s_c[j] + s_d[j];
            acc = fmaf(s_w2[j], gelu_exact(h), acc);
        }
        g_s[row] = acc + b2[0];
    }
#endif
}

// ---------------------------------------------------------------------------
// Kernel 2: per-segment softmax stats (max, sum of exp)
// ---------------------------------------------------------------------------
__global__ __launch_bounds__(256) void stats_kernel(const int* __restrict__ off)
{
    __shared__ float red[256];
    int s = blockIdx.x;
    int lo = off[s], hi = off[s + 1];
    int tid = threadIdx.x;

    float m = -1e30f;
    for (int i = lo + tid; i < hi; i += 256) m = fmaxf(m, g_s[i]);
    red[tid] = m;
    __syncthreads();
    for (int step = 128; step; step >>= 1) {
        if (tid < step) red[tid] = fmaxf(red[tid], red[tid + step]);
        __syncthreads();
    }
    float M = red[0];
    __syncthreads();

    float sum = 0.f;
    for (int i = lo + tid; i < hi; i += 256) sum += expf(g_s[i] - M);
    red[tid] = sum;
    __syncthreads();
    for (int step = 128; step; step >>= 1) {
        if (tid < step) red[tid] += red[tid + step];
        __syncthreads();
    }
    if (tid == 0) { g_smax[s] = M; g_den[s] = red[0]; }
}

// ---------------------------------------------------------------------------
// Kernel 3: chunked weighted pooling -> deterministic partials
// ---------------------------------------------------------------------------
__global__ __launch_bounds__(256) void pool1_kernel(
    const float* __restrict__ feats, const int* __restrict__ off)
{
    __shared__ float wsm[RD];
    int s = blockIdx.y, c = blockIdx.x;
    int lo = off[s], hi = off[s + 1];
    int tid = threadIdx.x;

    float M   = g_smax[s];
    float inv = 1.0f / g_den[s];
    float ax = 0.f, ay = 0.f, bx = 0.f, by = 0.f;

    for (int r0 = lo + c * RD; r0 < hi; r0 += MAXC * RD) {
        int cnt = min(RD, hi - r0);
        __syncthreads();
        for (int i = tid; i < cnt; i += 256) wsm[i] = expf(g_s[r0 + i] - M) * inv;
        __syncthreads();
        int r = 0;
        for (; r + 8 <= cnt; r += 8) {
#pragma unroll
            for (int u = 0; u < 8; u += 2) {
                float w0 = wsm[r + u], w1v = wsm[r + u + 1];
                float2 v0 = *(const float2*)(feats + (size_t)(r0 + r + u) * DIM + tid * 2);
                float2 v1 = *(const float2*)(feats + (size_t)(r0 + r + u + 1) * DIM + tid * 2);
                ax = fmaf(w0, v0.x, ax); ay = fmaf(w0, v0.y, ay);
                bx = fmaf(w1v, v1.x, bx); by = fmaf(w1v, v1.y, by);
            }
        }
        for (; r < cnt; r++) {
            float wv = wsm[r];
            float2 v = *(const float2*)(feats + (size_t)(r0 + r) * DIM + tid * 2);
            ax = fmaf(wv, v.x, ax); ay = fmaf(wv, v.y, ay);
        }
    }
    float* p = g_part + ((size_t)(s * MAXC + c)) * DIM;
    p[tid * 2]     = ax + bx;
    p[tid * 2 + 1] = ay + by;
}

// ---------------------------------------------------------------------------
// Kernel 4: reduce partials -> out
// ---------------------------------------------------------------------------
__global__ __launch_bounds__(256) void pool2_kernel(float* __restrict__ out)
{
    int s = blockIdx.x, tid = threadIdx.x;
    float ax = 0.f, ay = 0.f;
#pragma unroll
    for (int c = 0; c < MAXC; c++) {
        const float* p = g_part + ((size_t)(s * MAXC + c)) * DIM;
        ax += p[tid * 2];
        ay += p[tid * 2 + 1];
    }
    out[s * DIM + tid * 2]     = ax;
    out[s * DIM + tid * 2 + 1] = ay;
}

// ---------------------------------------------------------------------------
extern "C" void kernel_launch(void* const* d_in, const int* in_sizes, int n_in,
                              void* d_out, int out_size)
{
    const float* feats = (const float*)d_in[0];
    const float* lng   = (const float*)d_in[1];
    const float* lnb   = (const float*)d_in[2];
    const float* w1    = (const float*)d_in[3];
    const float* b1    = (const float*)d_in[4];
    const float* w2    = (const float*)d_in[5];
    const float* b2    = (const float*)d_in[6];
    const int*   off   = (const int*)d_in[7];
    float* out = (float*)d_out;

    static int attr_done = 0;
    if (!attr_done) {
        cudaFuncSetAttribute(score_fused, cudaFuncAttributeMaxDynamicSharedMemorySize, SM_TOTAL);
        attr_done = 1;
    }

    w1cvt_kernel<<<HID, 128>>>(w1, lng, lnb, b1);
    score_fused<<<N_PTS / MTILE, 512, SM_TOTAL>>>(feats, w2, b2);
    stats_kernel<<<NSEG, 256>>>(off);
    dim3 g1(MAXC, NSEG);
    pool1_kernel<<<g1, 256>>>(feats, off);
    pool2_kernel<<<NSEG, 256>>>(out);
}

// round 13
// speedup vs baseline: 2.3086x; 1.0882x over previous
#include <cuda_runtime.h>
#include <cuda_bf16.h>
#include <math.h>
#include <cstdint>

#define N_PTS   262144
#define DIM     512
#define HID     256
#define NSEG    64
#define LN_EPS  1e-5f

#define MTILE   128     // rows per score CTA
#define KC      64      // K-chunk (64 bf16 = 128 B row = SW128 atom width)
#define NCHUNK  (DIM / KC)
#define RD      256     // rows per pooling chunk
#define MAXC    16      // pooling chunks per segment

// ---------------- scratch (static device globals; no runtime allocation) ----
__device__ float          g_s[N_PTS];
__device__ float          g_smax[NSEG];
__device__ float          g_den[NSEG];
__device__ float          g_part[(size_t)NSEG * MAXC * DIM];
__device__ __nv_bfloat16  g_w1hi[HID * DIM];   // hi(w1*g)
__device__ __nv_bfloat16  g_w1lo[HID * DIM];   // lo(w1*g)
__device__ float          g_c[HID];            // sum_k w1[j,k]*g[k]
__device__ float          g_d[HID];            // sum_k w1[j,k]*beta[k] + b1[j]

// ---------------- helpers ---------------------------------------------------
__device__ __forceinline__ uint32_t smem_u32(const void* p) {
    uint32_t a;
    asm("{ .reg .u64 t; cvta.to.shared.u64 t, %1; cvt.u32.u64 %0, t; }"
        : "=r"(a) : "l"(p));
    return a;
}
#define SWZ128(o) ((o) ^ (((o) >> 3) & 0x70))

#define CP_ASYNC16(dst, src)                                                   \
    asm volatile("cp.async.cg.shared.global [%0], [%1], 16;" :: "r"(dst), "l"(src))
#define CP_COMMIT() asm volatile("cp.async.commit_group;" ::: "memory")
#define CP_WAIT0()  asm volatile("cp.async.wait_group 0;" ::: "memory")
#define FENCE_ASYNC() asm volatile("fence.proxy.async.shared::cta;" ::: "memory")

__device__ __forceinline__ uint32_t pack_bf2(float a, float b) {
    __nv_bfloat162 t = __floats2bfloat162_rn(a, b);
    return *(uint32_t*)&t;
}
__device__ __forceinline__ float gelu_exact(float h) {
    return 0.5f * h * (1.0f + erff(h * 0.70710678118654752f));
}

// ---------------- tcgen05 helpers (only compiled on sm_103a passes) ---------
#if defined(__CUDA_ARCH_FEAT_SM103_ALL) || defined(__CUDA_ARCH_FEAT_SM100_ALL) || defined(__CUDA_ARCH_FEAT_SM101_ALL)
#define HAVE_TCGEN05 1

__device__ __forceinline__ uint32_t elect_one() {
    uint32_t p;
    asm volatile("{\n\t.reg .pred p;\n\t"
                 "elect.sync _|p, 0xFFFFFFFF;\n\t"
                 "selp.b32 %0, 1, 0, p;\n\t}" : "=r"(p));
    return p;
}
static constexpr uint64_t DESC_BASE_SW128 =
    (uint64_t(2) << 61) | (uint64_t(1) << 46) | (uint64_t(64) << 32) | (uint64_t(1) << 16);
#define MAKE_DESC(addr) (DESC_BASE_SW128 | ((uint64_t)((addr) >> 4) & 0x3FFF))

#define MBAR_INIT(a, c) \
    asm volatile("mbarrier.init.shared.b64 [%0], %1;" :: "r"(a), "r"(c) : "memory")
#define MBAR_WAIT(a, ph) do {                                                  \
    uint32_t _m = (a), _p = (ph), _d;                                          \
    asm volatile("{\n\t.reg .pred p;\n\t"                                      \
        "mbarrier.try_wait.parity.acquire.cta.shared::cta.b64 p, [%1], %2;\n\t"\
        "selp.b32 %0, 1, 0, p;\n\t}" : "=r"(_d) : "r"(_m), "r"(_p) : "memory");\
    if (!_d) {                                                                 \
        asm volatile("{\n\t.reg .pred P1;\n\t"                                 \
          "W%=:\n\t"                                                           \
          "mbarrier.try_wait.parity.acquire.cta.shared::cta.b64 P1, [%0], %1, 0x989680;\n\t" \
          "@P1 bra.uni D%=;\n\t"                                               \
          "bra.uni W%=;\n\t"                                                   \
          "D%=:\n\t}" :: "r"(_m), "r"(_p) : "memory");                         \
    } } while (0)

#define TC_ALLOC(sa, n) \
    asm volatile("tcgen05.alloc.cta_group::1.sync.aligned.shared::cta.b32 [%0], %1;" \
                 :: "r"(sa), "r"(n) : "memory")
#define TC_RELINQ() \
    asm volatile("tcgen05.relinquish_alloc_permit.cta_group::1.sync.aligned;")
#define TC_DEALLOC(t, n) \
    asm volatile("tcgen05.dealloc.cta_group::1.sync.aligned.b32 %0, %1;" :: "r"(t), "r"(n))
#define TC_COMMIT(mb) \
    asm volatile("tcgen05.commit.cta_group::1.mbarrier::arrive::one.shared::cluster.b64 [%0];" \
                 :: "r"(mb) : "memory")
#define TC_FENCE_AFTER()  asm volatile("tcgen05.fence::after_thread_sync;"  ::: "memory")
#define TC_FENCE_BEFORE() asm volatile("tcgen05.fence::before_thread_sync;" ::: "memory")
#define TC_WAIT_LD()      asm volatile("tcgen05.wait::ld.sync.aligned;" ::: "memory")

#define TC_LD_X32(r, ta)                                                       \
    asm volatile("tcgen05.ld.sync.aligned.32x32b.x32.b32 "                     \
        "{%0, %1, %2, %3, %4, %5, %6, %7, "                                    \
        " %8, %9, %10, %11, %12, %13, %14, %15, "                              \
        " %16, %17, %18, %19, %20, %21, %22, %23, "                            \
        " %24, %25, %26, %27, %28, %29, %30, %31}, [%32];"                     \
        : "=r"((r)[0]),  "=r"((r)[1]),  "=r"((r)[2]),  "=r"((r)[3]),           \
          "=r"((r)[4]),  "=r"((r)[5]),  "=r"((r)[6]),  "=r"((r)[7]),           \
          "=r"((r)[8]),  "=r"((r)[9]),  "=r"((r)[10]), "=r"((r)[11]),          \
          "=r"((r)[12]), "=r"((r)[13]), "=r"((r)[14]), "=r"((r)[15]),          \
          "=r"((r)[16]), "=r"((r)[17]), "=r"((r)[18]), "=r"((r)[19]),          \
          "=r"((r)[20]), "=r"((r)[21]), "=r"((r)[22]), "=r"((r)[23]),          \
          "=r"((r)[24]), "=r"((r)[25]), "=r"((r)[26]), "=r"((r)[27]),          \
          "=r"((r)[28]), "=r"((r)[29]), "=r"((r)[30]), "=r"((r)[31])           \
        : "r"(ta))

__device__ __forceinline__ void tc_mma_f16_ss(uint32_t d, uint64_t a, uint64_t b,
                                              uint32_t idesc, bool acc) {
    uint32_t en = acc ? 1u : 0u;
    asm volatile("{\n\t.reg .pred p;\n\t"
                 "setp.ne.u32 p, %5, 0;\n\t"
                 "tcgen05.mma.cta_group::1.kind::f16 [%0], %1, %2, %3, {%4, %4, %4, %4}, p;\n\t}"
                 :: "r"(d), "l"(a), "l"(b), "r"(idesc), "r"(0u), "r"(en)
                 : "memory");
}
// idesc: dtype=F32, a=BF16, b=BF16, N=256, M=128
#define TC_IDESC ((1u << 4) | (1u << 7) | (1u << 10) | ((HID / 8) << 17) | ((MTILE / 16) << 24))
#endif  // tcgen05

// ---------------- smem layout (bytes) for score_fused -----------------------
// misc params < 8 KB, then SINGLE-buffered tiles (2 CTAs/SM fit: 104 KB each)
#define SM_MU    0        // 128 f32
#define SM_RS    512
#define SM_C     1024     // 256 f32: c_j
#define SM_D     2048     // 256 f32: d_j
#define SM_W2    3072     // 256 f32
#define SM_RED   4096     // 512 f32 (epilogue partials)
#define SM_TMEM  6144
#define SM_MBARB 6152
#define SM_A     8192     // AHI 16KB @ +0, ALO 16KB @ +16384 ; ends 40960
#define SM_A_LO  16384
#define SM_B     40960    // BHI 32KB @ +0, BLO 32KB @ +32768 ; ends 106496
#define SM_B_LO  32768
#define SM_TOTAL 106496   // x2 CTAs = 212992 <= 228KB carveout

// ---------------------------------------------------------------------------
// Kernel 0: w1 -> w1*g bf16 hi/lo, plus c_j = sum(w1*g), d_j = sum(w1*beta)+b1
// ---------------------------------------------------------------------------
__global__ __launch_bounds__(128) void w1cvt_kernel(
    const float* __restrict__ w1, const float* __restrict__ lng,
    const float* __restrict__ lnb, const float* __restrict__ b1)
{
    __shared__ float redc[4], redd[4];
    int j = blockIdx.x;
    int t = threadIdx.x;
    int c0 = t * 4;
    float csum = 0.f, dsum = 0.f;
#pragma unroll
    for (int k = 0; k < 4; k++) {
        int c = c0 + k;
        float w = w1[(size_t)j * DIM + c];
        float wt = w * lng[c];
        __nv_bfloat16 hi = __float2bfloat16_rn(wt);
        float lo = wt - __bfloat162float(hi);
        g_w1hi[(size_t)j * DIM + c] = hi;
        g_w1lo[(size_t)j * DIM + c] = __float2bfloat16_rn(lo);
        csum += wt;
        dsum += w * lnb[c];
    }
#pragma unroll
    for (int m = 16; m; m >>= 1) {
        csum += __shfl_xor_sync(0xffffffffu, csum, m);
        dsum += __shfl_xor_sync(0xffffffffu, dsum, m);
    }
    if ((t & 31) == 0) { redc[t >> 5] = csum; redd[t >> 5] = dsum; }
    __syncthreads();
    if (t == 0) {
        g_c[j] = redc[0] + redc[1] + redc[2] + redc[3];
        g_d[j] = redd[0] + redd[1] + redd[2] + redd[3] + b1[j];
    }
}

// ---------------------------------------------------------------------------
// Kernel 1: raw-feats bf16-split tcgen05 GEMM + LN-affine correction + GELU
//           + w2 dot -> g_s.  512 threads, 128x256 per CTA, 2 CTAs/SM.
// Single-buffered tiles; A prefetched + converted in registers BEFORE the
// mbarrier wait so DRAM latency overlaps the running MMA.
// ---------------------------------------------------------------------------
__global__ __launch_bounds__(512, 2)
void score_fused(const float* __restrict__ feats,
                 const float* __restrict__ w2,
                 const float* __restrict__ b2)
{
    extern __shared__ char smem[];
    uint32_t sb = smem_u32(smem);
    int tid  = threadIdx.x;
    int w    = tid >> 5, lane = tid & 31;
    int row0 = blockIdx.x * MTILE;

    float* s_mu  = (float*)(smem + SM_MU);
    float* s_rs  = (float*)(smem + SM_RS);
    float* s_c   = (float*)(smem + SM_C);
    float* s_d   = (float*)(smem + SM_D);
    float* s_w2  = (float*)(smem + SM_W2);
    float* s_red = (float*)(smem + SM_RED);

#ifdef HAVE_TCGEN05
    // =======================================================================
    // tcgen05 path (runs on GB300)
    // =======================================================================
    if (w == 0) { TC_ALLOC(sb + SM_TMEM, 256); TC_RELINQ(); }
    if (tid == 0) MBAR_INIT(sb + SM_MBARB, 1);

    // staging roles
    int arow = tid >> 2, aq = tid & 3;        // A: thread = (row, 16-col quarter)
    int brow = tid >> 1, bh = tid & 1;        // B: thread = (hid row, 32-col half)
    const float* aft = feats + (size_t)(row0 + arow) * DIM + aq * 16;

    uint32_t a_sw  = SWZ128((uint32_t)(arow * 128 + aq * 32));
    uint32_t a_sw2 = SWZ128((uint32_t)(arow * 128 + aq * 32 + 16));
    const __nv_bfloat16* bsrc_h = g_w1hi + (size_t)brow * DIM + bh * 32;
    const __nv_bfloat16* bsrc_l = g_w1lo + (size_t)brow * DIM + bh * 32;
    uint32_t b_sw[4];
#pragma unroll
    for (int j = 0; j < 4; j++) b_sw[j] = SWZ128((uint32_t)(brow * 128 + bh * 64 + j * 16));

#define STAGE_B(cc) do {                                                       \
        const __nv_bfloat16* sh_ = bsrc_h + (cc) * KC;                         \
        const __nv_bfloat16* sl_ = bsrc_l + (cc) * KC;                         \
        _Pragma("unroll")                                                      \
        for (int j = 0; j < 4; j++) {                                          \
            CP_ASYNC16(sb + SM_B + b_sw[j],           sh_ + j * 8);            \
            CP_ASYNC16(sb + SM_B + SM_B_LO + b_sw[j], sl_ + j * 8);            \
        }                                                                      \
    } while (0)

    float a_sum = 0.f, a_sq = 0.f;   // row-stat accumulators (this thread's slice)

    // PREP_A: load next chunk's feats + convert to bf16 hi/lo in registers.
    // No smem writes -> safe to run BEFORE the mbarrier wait (overlaps MMA).
#define PREP_A(cc, HP, LP) do {                                                \
        const float4* fr = (const float4*)(aft + (cc) * KC);                   \
        _Pragma("unroll")                                                      \
        for (int q_ = 0; q_ < 4; q_++) {                                       \
            float4 f = fr[q_];                                                 \
            a_sum += f.x + f.y + f.z + f.w;                                    \
            a_sq  += f.x * f.x + f.y * f.y + f.z * f.z + f.w * f.w;            \
            __nv_bfloat162 h01 = __floats2bfloat162_rn(f.x, f.y);              \
            __nv_bfloat162 h23 = __floats2bfloat162_rn(f.z, f.w);              \
            (HP)[q_ * 2]     = *(uint32_t*)&h01;                               \
            (HP)[q_ * 2 + 1] = *(uint32_t*)&h23;                               \
            (LP)[q_ * 2]     = pack_bf2(f.x - __bfloat162float(h01.x),         \
                                        f.y - __bfloat162float(h01.y));        \
            (LP)[q_ * 2 + 1] = pack_bf2(f.z - __bfloat162float(h23.x),         \
                                        f.w - __bfloat162float(h23.y));        \
        }                                                                      \
    } while (0)

    // STORE_A: write the prepared registers into the (now free) A tile.
#define STORE_A(HP, LP) do {                                                   \
        *(uint4*)(smem + SM_A + a_sw)            = *(uint4*)&(HP)[0];          \
        *(uint4*)(smem + SM_A + a_sw2)           = *(uint4*)&(HP)[4];          \
        *(uint4*)(smem + SM_A + SM_A_LO + a_sw)  = *(uint4*)&(LP)[0];          \
        *(uint4*)(smem + SM_A + SM_A_LO + a_sw2) = *(uint4*)&(LP)[4];          \
    } while (0)

    // ---- prologue: stage chunk 0, load params ----
    uint32_t hp[8], lp[8];
    STAGE_B(0);
    CP_COMMIT();
    PREP_A(0, hp, lp);
    STORE_A(hp, lp);
    for (int i = tid; i < HID; i += 512) { s_c[i] = g_c[i]; s_d[i] = g_d[i]; s_w2[i] = w2[i]; }
    CP_WAIT0();
    FENCE_ASYNC();
    __syncthreads();

    uint32_t tmem;
    asm volatile("ld.shared.b32 %0, [%1];" : "=r"(tmem) : "r"(sb + SM_TMEM));

    for (int c = 0; c < NCHUNK; c++) {
        // issue 12 MMA dispatches for chunk c (buffers staged & fenced)
        if (w == 0 && elect_one()) {
            uint64_t adh = MAKE_DESC(sb + SM_A);
            uint64_t adl = MAKE_DESC(sb + SM_A + SM_A_LO);
            uint64_t bdh = MAKE_DESC(sb + SM_B);
            uint64_t bdl = MAKE_DESC(sb + SM_B + SM_B_LO);
#pragma unroll
            for (int s = 0; s < 4; s++)
                tc_mma_f16_ss(tmem, adh + s * 2, bdh + s * 2, TC_IDESC, !(c == 0 && s == 0));
#pragma unroll
            for (int s = 0; s < 4; s++)
                tc_mma_f16_ss(tmem, adh + s * 2, bdl + s * 2, TC_IDESC, true);
#pragma unroll
            for (int s = 0; s < 4; s++)
                tc_mma_f16_ss(tmem, adl + s * 2, bdh + s * 2, TC_IDESC, true);
            TC_COMMIT(sb + SM_MBARB);
        }
        // prefetch + convert A(c+1) in registers while MMA(c) runs
        if (c + 1 < NCHUNK) PREP_A(c + 1, hp, lp);
        // wait MMA(c) done -> single buffers free to restage
        MBAR_WAIT(sb + SM_MBARB, c & 1);
        if (c + 1 < NCHUNK) {
            STAGE_B(c + 1);
            CP_COMMIT();
            STORE_A(hp, lp);
            CP_WAIT0();
            FENCE_ASYNC();
        }
        __syncthreads();
    }

    // finalize row stats (quad-reduce: lanes aq=0..3 share row)
    a_sum += __shfl_xor_sync(0xffffffffu, a_sum, 1);
    a_sq  += __shfl_xor_sync(0xffffffffu, a_sq,  1);
    a_sum += __shfl_xor_sync(0xffffffffu, a_sum, 2);
    a_sq  += __shfl_xor_sync(0xffffffffu, a_sq,  2);
    if ((lane & 3) == 0) {
        float mu = a_sum * (1.0f / DIM);
        float var = a_sq * (1.0f / DIM) - mu * mu;
        s_mu[arow] = mu;
        s_rs[arow] = rsqrtf(var + LN_EPS);
    }
    TC_FENCE_AFTER();
    __syncthreads();

    // --- epilogue: 16 warps; warp w -> rows (w&3)*32, cols (w>>2)*64 ---
    // one LDTM.x32 in flight at a time (64-reg cap at 2 CTAs/SM)
    {
        int rsub = w & 3, q = w >> 2;
        int row = rsub * 32 + lane;
        float rs = s_rs[row];
        float nrsmu = -rs * s_mu[row];
        float acc = 0.f;
#pragma unroll
        for (int half = 0; half < 2; half++) {
            uint32_t r_[32];
            TC_LD_X32(r_, tmem + q * 64 + half * 32);
            TC_WAIT_LD();
#pragma unroll
            for (int j = 0; j < 32; j++) {
                int col = q * 64 + half * 32 + j;
                float h = fmaf(rs, __uint_as_float(r_[j]), fmaf(nrsmu, s_c[col], s_d[col]));
                acc = fmaf(s_w2[col], gelu_exact(h), acc);
            }
        }
        TC_FENCE_BEFORE();
        s_red[q * 128 + row] = acc;
    }
    __syncthreads();
    if (tid < MTILE) {
        float s = s_red[tid] + s_red[128 + tid] + s_red[256 + tid] + s_red[384 + tid];
        g_s[row0 + tid] = s + b2[0];
    }
    if (w == 0) TC_DEALLOC(tmem, 256);

#else
    // =======================================================================
    // non-sm_103a fallback: trivially correct scalar path (never runs on GB300)
    // =======================================================================
    for (int i = tid; i < HID; i += 512) { s_c[i] = g_c[i]; s_d[i] = g_d[i]; s_w2[i] = w2[i]; }
    __syncthreads();
    if (tid < MTILE) {
        int row = row0 + tid;
        const float* fr = feats + (size_t)row * DIM;
        float sum = 0.f, sq = 0.f;
        for (int k = 0; k < DIM; k++) { float v = fr[k]; sum += v; sq += v * v; }
        float mu = sum * (1.0f / DIM);
        float rs = rsqrtf(sq * (1.0f / DIM) - mu * mu + LN_EPS);
        float acc = 0.f;
        for (int j = 0; j < HID; j++) {
            float dot = 0.f;
            for (int k = 0; k < DIM; k++) {
                float wt = __bfloat162float(g_w1hi[(size_t)j * DIM + k]) +
                           __bfloat162float(g_w1lo[(size_t)j * DIM + k]);
                dot = fmaf(wt, fr[k], dot);
            }
            float h = rs * dot - rs * mu * s_c[j] + s_d[j];
            acc = fmaf(s_w2[j], gelu_exact(h), acc);
        }
        g_s[row] = acc + b2[0];
    }
#endif
}

// ---------------------------------------------------------------------------
// Kernel 2: per-segment softmax stats (max, sum of exp)
// ---------------------------------------------------------------------------
__global__ __launch_bounds__(256) void stats_kernel(const int* __restrict__ off)
{
    __shared__ float red[256];
    int s = blockIdx.x;
    int lo = off[s], hi = off[s + 1];
    int tid = threadIdx.x;

    float m = -1e30f;
    for (int i = lo + tid; i < hi; i += 256) m = fmaxf(m, g_s[i]);
    red[tid] = m;
    __syncthreads();
    for (int step = 128; step; step >>= 1) {
        if (tid < step) red[tid] = fmaxf(red[tid], red[tid + step]);
        __syncthreads();
    }
    float M = red[0];
    __syncthreads();

    float sum = 0.f;
    for (int i = lo + tid; i < hi; i += 256) sum += expf(g_s[i] - M);
    red[tid] = sum;
    __syncthreads();
    for (int step = 128; step; step >>= 1) {
        if (tid < step) red[tid] += red[tid + step];
        __syncthreads();
    }
    if (tid == 0) { g_smax[s] = M; g_den[s] = red[0]; }
}

// ---------------------------------------------------------------------------
// Kernel 3: chunked weighted pooling -> deterministic partials
// ---------------------------------------------------------------------------
__global__ __launch_bounds__(256) void pool1_kernel(
    const float* __restrict__ feats, const int* __restrict__ off)
{
    __shared__ float wsm[RD];
    int s = blockIdx.y, c = blockIdx.x;
    int lo = off[s], hi = off[s + 1];
    int tid = threadIdx.x;

    float M   = g_smax[s];
    float inv = 1.0f / g_den[s];
    float ax = 0.f, ay = 0.f, bx = 0.f, by = 0.f;

    for (int r0 = lo + c * RD; r0 < hi; r0 += MAXC * RD) {
        int cnt = min(RD, hi - r0);
        __syncthreads();
        for (int i = tid; i < cnt; i += 256) wsm[i] = expf(g_s[r0 + i] - M) * inv;
        __syncthreads();
        int r = 0;
        for (; r + 8 <= cnt; r += 8) {
#pragma unroll
            for (int u = 0; u < 8; u += 2) {
                float w0 = wsm[r + u], w1v = wsm[r + u + 1];
                float2 v0 = *(const float2*)(feats + (size_t)(r0 + r + u) * DIM + tid * 2);
                float2 v1 = *(const float2*)(feats + (size_t)(r0 + r + u + 1) * DIM + tid * 2);
                ax = fmaf(w0, v0.x, ax); ay = fmaf(w0, v0.y, ay);
                bx = fmaf(w1v, v1.x, bx); by = fmaf(w1v, v1.y, by);
            }
        }
        for (; r < cnt; r++) {
            float wv = wsm[r];
            float2 v = *(const float2*)(feats + (size_t)(r0 + r) * DIM + tid * 2);
            ax = fmaf(wv, v.x, ax); ay = fmaf(wv, v.y, ay);
        }
    }
    float* p = g_part + ((size_t)(s * MAXC + c)) * DIM;
    p[tid * 2]     = ax + bx;
    p[tid * 2 + 1] = ay + by;
}

// ---------------------------------------------------------------------------
// Kernel 4: reduce partials -> out
// ---------------------------------------------------------------------------
__global__ __launch_bounds__(256) void pool2_kernel(float* __restrict__ out)
{
    int s = blockIdx.x, tid = threadIdx.x;
    float ax = 0.f, ay = 0.f;
#pragma unroll
    for (int c = 0; c < MAXC; c++) {
        const float* p = g_part + ((size_t)(s * MAXC + c)) * DIM;
        ax += p[tid * 2];
        ay += p[tid * 2 + 1];
    }
    out[s * DIM + tid * 2]     = ax;
    out[s * DIM + tid * 2 + 1] = ay;
}

// ---------------------------------------------------------------------------
extern "C" void kernel_launch(void* const* d_in, const int* in_sizes, int n_in,
                              void* d_out, int out_size)
{
    const float* feats = (const float*)d_in[0];
    const float* lng   = (const float*)d_in[1];
    const float* lnb   = (const float*)d_in[2];
    const float* w1    = (const float*)d_in[3];
    const float* b1    = (const float*)d_in[4];
    const float* w2    = (const float*)d_in[5];
    const float* b2    = (const float*)d_in[6];
    const int*   off   = (const int*)d_in[7];
    float* out = (float*)d_out;

    static int attr_done = 0;
    if (!attr_done) {
        cudaFuncSetAttribute(score_fused, cudaFuncAttributeMaxDynamicSharedMemorySize, SM_TOTAL);
        attr_done = 1;
    }

    w1cvt_kernel<<<HID, 128>>>(w1, lng, lnb, b1);
    score_fused<<<N_PTS / MTILE, 512, SM_TOTAL>>>(feats, w2, b2);
    stats_kernel<<<NSEG, 256>>>(off);
    dim3 g1(MAXC, NSEG);
    pool1_kernel<<<g1, 256>>>(feats, off);
    pool2_kernel<<<NSEG, 256>>>(out);
}